// round 14
// baseline (speedup 1.0000x reference)
#include <cuda_runtime.h>
#include <cuda_fp16.h>
#include <math.h>
#include <stdint.h>

#define NN   100000
#define NNP  100096      // 782 * 128
#define NG   1000
#define NS   100
#define NE   99000
#define FIN  512
#define HIDD 128
#define FO   64

// ---------------- scratch (device globals; no allocations allowed) ----------------
__device__ __align__(16) __half g_x16[NNP * FIN];               // x in fp16 (rows >= NN stay 0)
__device__ __align__(16) __half g_hxh[NNP * FIN];               // A_z fp16
__device__ __align__(16) float g_root[NG * FIN];                // fp32 root hx rows
__device__ __align__(16) float g_cat1[NNP * 256];               // [td1 | bu1] GEMM output
__device__ __align__(16) __half g_waT[FIN * FIN];
__device__ __align__(16) __half g_wcT[256 * FIN];
__device__ __align__(16) __half g_zpm[NG * FIN];
__device__ __align__(16) __half g_zpa[NG * FIN];
__device__ __align__(16) float g_tp[2 * NG * HIDD];
__device__ __align__(16) float g_tln[2 * NG * HIDD];
__device__ __align__(16) float g_pm[2 * NG * FIN];
__device__ __align__(16) float g_alpha[NG];
__device__ __align__(16) float g_stats[4];
__device__ __align__(16) int   g_cnt[NN];
__device__ __align__(16) int   g_parent[NN];
__device__ int   g_idx64;

// ---------------- helpers ----------------
static __device__ __forceinline__ uint32_t smem_u32(const void* p) {
    uint32_t a;
    asm("{ .reg .u64 t; cvta.to.shared.u64 t, %1; cvt.u32.u64 %0, t; }" : "=r"(a) : "l"(p));
    return a;
}
#define CP_ASYNC16(dst_u32, src) \
    asm volatile("cp.async.cg.shared.global [%0], [%1], 16;" :: "r"(dst_u32), "l"(src))
#define CP_COMMIT() asm volatile("cp.async.commit_group;" ::: "memory")
#define CP_WAIT1()  asm volatile("cp.async.wait_group 1;" ::: "memory")

#define MMA_F16(d, a, b0, b1) \
    asm volatile("mma.sync.aligned.m16n8k16.row.col.f32.f16.f16.f32 " \
        "{%0,%1,%2,%3}, {%4,%5,%6,%7}, {%8,%9}, {%0,%1,%2,%3};" \
        : "+f"((d)[0]), "+f"((d)[1]), "+f"((d)[2]), "+f"((d)[3]) \
        : "r"((a)[0]), "r"((a)[1]), "r"((a)[2]), "r"((a)[3]), "r"(b0), "r"(b1))

#define LDSM_X4(r, addr) \
    asm volatile("ldmatrix.sync.aligned.m8n8.x4.shared.b16 {%0,%1,%2,%3}, [%4];" \
        : "=r"((r)[0]), "=r"((r)[1]), "=r"((r)[2]), "=r"((r)[3]) : "r"(addr))

// ---------------- index dtype probe + edge accessors ----------------
__global__ void k_detect(const int* batch) {
    if (threadIdx.x == 0) g_idx64 = (batch[150] == 1) ? 0 : 1;
}
__device__ __forceinline__ int esrc(const void* ei, int e) {
    return g_idx64 ? (int)((const long long*)ei)[e] : ((const int*)ei)[e];
}
__device__ __forceinline__ int edst(const void* ei, int e) {
    return g_idx64 ? (int)((const long long*)ei)[NE + e] : ((const int*)ei)[NE + e];
}

// ---------------- small graph kernels ----------------
__global__ void k_zero() {
    int i = blockIdx.x * blockDim.x + threadIdx.x;
    if (i < NN) g_cnt[i] = 0;
    if (i < 4) g_stats[i] = 0.f;
}
__global__ void k_count(const void* ei) {
    int e = blockIdx.x * blockDim.x + threadIdx.x;
    if (e >= NE) return;
    int s = esrc(ei, e), d = edst(ei, e);
    atomicAdd(&g_cnt[s], 1);
    g_parent[d] = s;
}
__global__ void k_alpha() {
    int g = blockIdx.x * blockDim.x + threadIdx.x;
    if (g >= NG) return;
    float cnt = (float)g_cnt[g * NS];
    float t = (cnt / (float)NS - 0.3f) / 0.1f;
    g_alpha[g] = 1.f / (1.f + expf(-t));
}

// ---------------- preps ----------------
__global__ void k_wprep(const float* __restrict__ w, __half* __restrict__ hi, int K, int Nw) {
    int i = blockIdx.x * blockDim.x + threadIdx.x;
    if (i >= K * Nw) return;
    int k = i / Nw, n = i % Nw;
    hi[(size_t)n * K + k] = __float2half(w[i]);
}
__global__ void k_xprep(const float* __restrict__ x, __half* __restrict__ x16) {
    int i = blockIdx.x * blockDim.x + threadIdx.x;   // over NN*FIN/8
    if (i >= NN * FIN / 8) return;
    float4 a = ((const float4*)x)[i * 2];
    float4 b = ((const float4*)x)[i * 2 + 1];
    union { __half h[8]; uint4 u; } H;
    H.h[0] = __float2half(a.x); H.h[1] = __float2half(a.y);
    H.h[2] = __float2half(a.z); H.h[3] = __float2half(a.w);
    H.h[4] = __float2half(b.x); H.h[5] = __float2half(b.y);
    H.h[6] = __float2half(b.z); H.h[7] = __float2half(b.w);
    ((uint4*)x16)[i] = H.u;
}
__global__ void k_zprep(__half* __restrict__ zpm, __half* __restrict__ zpa) {
    int i = blockIdx.x * blockDim.x + threadIdx.x;
    if (i >= NG * FIN) return;
    int g = i / FIN;
    float a = g_alpha[g];
    zpm[i] = __float2half((1.f - a) * g_pm[i] + a);
    zpa[i] = __float2half(a * g_pm[NG * FIN + i]);
}

// ---------------- HMMA GEMM, fp16, 4 warps x 64x64 tiles, 3-stage, 1 barrier/iter ----
// MODE 0 (root):    A rows gathered (r -> r*NS); epilogue -> fp32 rootOut (r<NG).
// MODE 1 (adapter): A = x16; epilogue bias+leakyrelu+z -> fp16 Ch.
// MODE 2 (gemm1):   A = A_z; fp32 C epilogue.
template <int MODE>
__global__ void __launch_bounds__(128, 2) mmagemm(
    const __half* __restrict__ Asrc, const __half* __restrict__ Bh,
    const float* __restrict__ bias,
    const __half* __restrict__ zpm, const __half* __restrict__ zpa,
    __half* __restrict__ Ch, float* __restrict__ rootOut, float* __restrict__ C,
    int Ntot, int K)
{
    constexpr int ASZ = 128 * 40;       // elems per stage buffer (10240 B)
    extern __shared__ __align__(16) __half sm[];
    __half* sA = sm;                           // [0, 30720): 3 stages
    __half* sB = sm + 3 * ASZ;                 // [30720, 61440): 3 stages

    const int tid = threadIdx.x, lane = tid & 31, w = tid >> 5;   // 4 warps
    const int m0 = blockIdx.y * 128, n0 = blockIdx.x * 128;
    const int warpM = (w & 1) * 64;
    const int warpN = (w >> 1) * 64;
    const int r4 = lane >> 2, q = lane & 3;

    float acc[4][8][4];
#pragma unroll
    for (int mt = 0; mt < 4; mt++)
#pragma unroll
        for (int nt = 0; nt < 8; nt++)
#pragma unroll
            for (int i = 0; i < 4; i++) acc[mt][nt][i] = 0.f;

    const int KS = K >> 5;

    auto stage = [&](int ks, int s) {
#pragma unroll
        for (int c = tid; c < 512; c += 128) {     // A tile: 128 rows x 4 chunks
            int r = c >> 2, qq = c & 3;
            int srow = (MODE == 0) ? min(m0 + r, NG - 1) * NS : (m0 + r);
            const __half* src = Asrc + (size_t)srow * K + ks * 32 + qq * 8;
            CP_ASYNC16(smem_u32(sA + s * ASZ + r * 40) + qq * 16, src);
        }
#pragma unroll
        for (int c = tid; c < 512; c += 128) {     // B tile
            int r = c >> 2, qq = c & 3;
            const __half* src = Bh + (size_t)(n0 + r) * K + ks * 32 + qq * 8;
            CP_ASYNC16(smem_u32(sB + s * ASZ + r * 40) + qq * 16, src);
        }
    };

    // ldmatrix per-lane base addresses
    const int mat = lane >> 3, mrow = lane & 7;
    const uint32_t smb = smem_u32(sm);
    const uint32_t aBase = smb + (uint32_t)((warpM + (mat & 1) * 8 + mrow) * 80 + (mat >> 1) * 16);
    const uint32_t bBase = smb + 30720u + (uint32_t)((warpN + (mat & 1) * 8 + mrow) * 80 + (mat >> 1) * 16);

    // ---- prologue ----
    stage(0, 0); CP_COMMIT();
    stage(1, 1); CP_COMMIT();
    CP_WAIT1();
    __syncthreads();

    for (int ks = 0; ks < KS; ks++) {
        const int s = ks % 3;
        const bool pre = (ks + 2 < KS);
        if (pre) {
            stage(ks + 2, (ks + 2) % 3);
            CP_COMMIT();
        } else {
            CP_COMMIT();
        }

        const uint32_t aS = aBase + (uint32_t)s * 10240u;
        const uint32_t bS = bBase + (uint32_t)s * 10240u;
#pragma unroll
        for (int k16 = 0; k16 < 2; k16++) {
            uint32_t ah[4][4];
#pragma unroll
            for (int mt = 0; mt < 4; mt++)
                LDSM_X4(ah[mt], aS + mt * 1280u + k16 * 32u);
            uint32_t bp[2][4];
            LDSM_X4(bp[0], bS + k16 * 32u);
#pragma unroll
            for (int nn = 0; nn < 4; nn++) {       // B fragment ping-pong
                const int cur = nn & 1;
                if (nn < 3) LDSM_X4(bp[cur ^ 1], bS + (nn + 1) * 1280u + k16 * 32u);
#pragma unroll
                for (int e = 0; e < 2; e++) {
                    const int nt = 2 * nn + e;
#pragma unroll
                    for (int mt = 0; mt < 4; mt++)
                        MMA_F16(acc[mt][nt], ah[mt], bp[cur][e], bp[cur][e + 2]);
                }
            }
        }
        CP_WAIT1();
        __syncthreads();
    }

    // ---- epilogue ----
#pragma unroll
    for (int mt = 0; mt < 4; mt++) {
#pragma unroll
        for (int nt = 0; nt < 8; nt++) {
            int row = m0 + warpM + mt * 16 + r4;
            int col = n0 + warpN + nt * 8 + q * 2;
            float v0 = acc[mt][nt][0], v1 = acc[mt][nt][1];
            float v2 = acc[mt][nt][2], v3 = acc[mt][nt][3];
            if (MODE == 0) {
                float b0 = bias[col], b1 = bias[col + 1];
                v0 += b0; v1 += b1; v2 += b0; v3 += b1;
                v0 = v0 > 0.f ? v0 : 0.01f * v0;
                v1 = v1 > 0.f ? v1 : 0.01f * v1;
                v2 = v2 > 0.f ? v2 : 0.01f * v2;
                v3 = v3 > 0.f ? v3 : 0.01f * v3;
                if (row < NG)
                    *(float2*)(rootOut + (size_t)row * FIN + col) = make_float2(v0, v1);
                if (row + 8 < NG)
                    *(float2*)(rootOut + (size_t)(row + 8) * FIN + col) = make_float2(v2, v3);
            } else if (MODE == 1) {
                float b0 = bias[col], b1 = bias[col + 1];
                v0 += b0; v1 += b1; v2 += b0; v3 += b1;
                v0 = v0 > 0.f ? v0 : 0.01f * v0;
                v1 = v1 > 0.f ? v1 : 0.01f * v1;
                v2 = v2 > 0.f ? v2 : 0.01f * v2;
                v3 = v3 > 0.f ? v3 : 0.01f * v3;
                int ga = row / NS, gb2 = (row + 8) / NS;
                float2 fm0 = __half22float2(*(const __half2*)(zpm + (size_t)ga * FIN + col));
                float2 fa0 = __half22float2(*(const __half2*)(zpa + (size_t)ga * FIN + col));
                float2 fm1 = __half22float2(*(const __half2*)(zpm + (size_t)gb2 * FIN + col));
                float2 fa1 = __half22float2(*(const __half2*)(zpa + (size_t)gb2 * FIN + col));
                v0 = v0 * fm0.x + fa0.x; v1 = v1 * fm0.y + fa0.y;
                v2 = v2 * fm1.x + fa1.x; v3 = v3 * fm1.y + fa1.y;
                *(__half2*)(Ch + (size_t)row * Ntot + col) = __floats2half2_rn(v0, v1);
                *(__half2*)(Ch + (size_t)(row + 8) * Ntot + col) = __floats2half2_rn(v2, v3);
            } else {
                *(float2*)(C + (size_t)row * Ntot + col) = make_float2(v0, v1);
                *(float2*)(C + (size_t)(row + 8) * Ntot + col) = make_float2(v2, v3);
            }
        }
    }
}

// ---------------- prompt kernels (8 graphs per block) ----------------
__global__ void k_promptA(const float* __restrict__ w1a, const float* __restrict__ b1a,
                          const float* __restrict__ w1b, const float* __restrict__ b1b) {
    const int gb = blockIdx.x * 8, which = blockIdx.y, j = threadIdx.x;  // 128 threads
    const float* w = which ? w1b : w1a;
    const float* b = which ? b1b : b1a;
    __shared__ float rfs[8 * 128];
    float acc[8];
    float bj = b[j];
#pragma unroll
    for (int g = 0; g < 8; g++) acc[g] = bj;
    for (int kc = 0; kc < 4; kc++) {
        __syncthreads();
#pragma unroll
        for (int idx = j; idx < 1024; idx += 128) {
            int g = idx >> 7, k = idx & 127;
            rfs[idx] = g_root[(size_t)(gb + g) * FIN + kc * 128 + k];
        }
        __syncthreads();
#pragma unroll 2
        for (int k = 0; k < 128; k++) {
            float wv = w[(kc * 128 + k) * HIDD + j];
#pragma unroll
            for (int g = 0; g < 8; g++)
                acc[g] = fmaf(rfs[g * 128 + k], wv, acc[g]);
        }
    }
    float l1 = 0.f, l2 = 0.f;
#pragma unroll
    for (int g = 0; g < 8; g++) {
        g_tp[which * NG * HIDD + (gb + g) * HIDD + j] = acc[g];
        l1 += acc[g];
        l2 += acc[g] * acc[g];
    }
    __shared__ float s1[128], s2[128];
    s1[j] = l1; s2[j] = l2;
    __syncthreads();
    for (int o = 64; o > 0; o >>= 1) {
        if (j < o) { s1[j] += s1[j + o]; s2[j] += s2[j + o]; }
        __syncthreads();
    }
    if (j == 0) {
        atomicAdd(&g_stats[which * 2 + 0], s1[0]);
        atomicAdd(&g_stats[which * 2 + 1], s2[0]);
    }
}
__global__ void k_promptLN(const float* __restrict__ lnwa, const float* __restrict__ lnba,
                           const float* __restrict__ lnwb, const float* __restrict__ lnbb) {
    int g = blockIdx.x, which = blockIdx.y, j = threadIdx.x;
    const float* lw = which ? lnwb : lnwa;
    const float* lb = which ? lnbb : lnba;
    const float inv_n = 1.f / (float)(NG * HIDD);
    float m = g_stats[which * 2 + 0] * inv_n;
    float msq = fmaxf(g_stats[which * 2 + 1] * inv_n - m * m, 0.f);
    float denom = sqrtf(msq) + 1e-5f;
    float t = g_tp[which * NG * HIDD + g * HIDD + j];
    float v = (t - m) / denom * lw[j] + lb[j];
    g_tln[which * NG * HIDD + g * HIDD + j] = tanhf(v);
}
__global__ void k_promptB(const float* __restrict__ w2a, const float* __restrict__ b2a,
                          const float* __restrict__ w2b, const float* __restrict__ b2b) {
    const int gb = blockIdx.x * 8, which = blockIdx.y, j = threadIdx.x;  // 512 threads
    const float* w = which ? w2b : w2a;
    const float* b = which ? b2b : b2a;
    __shared__ float ts[8 * 128];
#pragma unroll
    for (int idx = j; idx < 1024; idx += 512) {
        int g = idx >> 7, k = idx & 127;
        ts[idx] = g_tln[which * NG * HIDD + (gb + g) * HIDD + k];
    }
    __syncthreads();
    float acc[8];
    float bj = b[j];
#pragma unroll
    for (int g = 0; g < 8; g++) acc[g] = bj;
#pragma unroll 2
    for (int k = 0; k < 128; k++) {
        float wv = w[k * FIN + j];
#pragma unroll
        for (int g = 0; g < 8; g++)
            acc[g] = fmaf(ts[g * 128 + k], wv, acc[g]);
    }
#pragma unroll
    for (int g = 0; g < 8; g++)
        g_pm[which * NG * FIN + (gb + g) * FIN + j] = acc[g];
}

// ---------------- fused tail: layer2 + small GEMM + projA + projB ----------------
__global__ void k_tail(const float* __restrict__ td1_b, const float* __restrict__ bu1_b,
                       const float* __restrict__ w2td, const float* __restrict__ td2_b,
                       const float* __restrict__ w2bu, const float* __restrict__ bu2_b,
                       const float* __restrict__ pw1, const float* __restrict__ pb1,
                       const float* __restrict__ pw2, const float* __restrict__ pb2,
                       float* __restrict__ out) {
    extern __shared__ float buacc[];            // [NS][128]
    __shared__ float dinvb[NS], cntS[NS];
    __shared__ int   pl[NS];
    __shared__ float sS[256];                   // [s_td | s_bu]
    __shared__ float hc[128];                   // hcat
    __shared__ float r1s[256];
    const int g = blockIdx.x, t = threadIdx.x;  // 256 threads
    for (int n = t; n < NS; n += 256) {
        int i = g * NS + n;
        int c = g_cnt[i];
        cntS[n]  = (float)c;
        dinvb[n] = rsqrtf((float)(c + 1));
        pl[n]    = n ? (g_parent[i] - g * NS) : 0;
    }
    __syncthreads();
    // ---- phase 1: layer-1 aggregation + layer-2 collapse ----
    if (t < 128) {
        const int f = t;
        const float btd = td1_b[f];
        float s_td = 0.f;
        for (int n = 0; n < NS; n++) {
            float utd = g_cat1[(size_t)(g * NS + n) * 256 + f];
            float v, c_td;
            if (n) {
                int p = pl[n];
                float dp = p ? 0.70710678118654752f : 1.0f;
                float up = g_cat1[(size_t)(g * NS + p) * 256 + f];
                v = utd * 0.5f + up * dp * 0.70710678118654752f + btd;
                c_td = 0.5f + 0.5f * cntS[n];
            } else {
                v = utd + btd;
                c_td = 1.0f + 0.70710678118654752f * cntS[0];
            }
            v = v > 0.f ? v : 0.f;
            s_td += c_td * v;
        }
        sS[f] = s_td;
    } else {
        const int f = t - 128;
        const float bbu = bu1_b[f];
        for (int n = 0; n < NS; n++) {
            float ubu = g_cat1[(size_t)(g * NS + n) * 256 + 128 + f];
            float db = dinvb[n];
            if (n) {
                buacc[pl[n] * 128 + f] += ubu * db * dinvb[pl[n]];
                buacc[n * 128 + f] = ubu * db * db;
            } else {
                buacc[f] = ubu * db * db;
            }
        }
        float s_bu = 0.f;
        for (int n = 0; n < NS; n++) {
            float v = buacc[n * 128 + f] + bbu;
            v = v > 0.f ? v : 0.f;
            float db = dinvb[n];
            float c_bu = db * db + (n ? db * dinvb[pl[n]] : 0.f);
            s_bu += c_bu * v;
        }
        sS[128 + f] = s_bu;
    }
    __syncthreads();
    // ---- phase 2: small layer-2 GEMM -> hc ----
    if (t < 128) {
        float acc;
        if (t < FO) {
            acc = (float)NS * bu2_b[t];
#pragma unroll 4
            for (int k = 0; k < HIDD; k++) acc = fmaf(sS[128 + k], w2bu[k * FO + t], acc);
        } else {
            int jj = t - FO;
            acc = (float)NS * td2_b[jj];
#pragma unroll 4
            for (int k = 0; k < HIDD; k++) acc = fmaf(sS[k], w2td[k * FO + jj], acc);
        }
        hc[t] = acc;
    }
    __syncthreads();
    // ---- phase 3: projA -> r1s ----
    {
        float acc = pb1[t];
#pragma unroll 4
        for (int k = 0; k < 128; k++) acc = fmaf(hc[k], pw1[k * 256 + t], acc);
        r1s[t] = acc > 0.f ? acc : 0.f;
    }
    __syncthreads();
    // ---- phase 4: projB -> out ----
    if (t < 128) {
        float acc = pb2[t];
#pragma unroll 4
        for (int k = 0; k < 256; k++) acc = fmaf(r1s[k], pw2[k * 128 + t], acc);
        out[g * 128 + t] = acc;
    }
}

// ---------------- launch ----------------
extern "C" void kernel_launch(void* const* d_in, const int* in_sizes, int n_in,
                              void* d_out, int out_size) {
    const float* x         = (const float*)d_in[0];
    const void*  ei        = d_in[1];
    const int*   batch     = (const int*)d_in[2];
    const float* adapter_w = (const float*)d_in[3];
    const float* adapter_b = (const float*)d_in[4];
    const float* p1_w1 = (const float*)d_in[5];
    const float* p1_b1 = (const float*)d_in[6];
    const float* p1_lnw = (const float*)d_in[7];
    const float* p1_lnb = (const float*)d_in[8];
    const float* p1_w2 = (const float*)d_in[9];
    const float* p1_b2 = (const float*)d_in[10];
    const float* p2_w1 = (const float*)d_in[11];
    const float* p2_b1 = (const float*)d_in[12];
    const float* p2_lnw = (const float*)d_in[13];
    const float* p2_lnb = (const float*)d_in[14];
    const float* p2_w2 = (const float*)d_in[15];
    const float* p2_b2 = (const float*)d_in[16];
    const float* td1_w = (const float*)d_in[17];
    const float* td1_b = (const float*)d_in[18];
    const float* td2_w = (const float*)d_in[19];
    const float* td2_b = (const float*)d_in[20];
    const float* bu1_w = (const float*)d_in[21];
    const float* bu1_b = (const float*)d_in[22];
    const float* bu2_w = (const float*)d_in[23];
    const float* bu2_b = (const float*)d_in[24];
    const float* proj_w1 = (const float*)d_in[25];
    const float* proj_b1 = (const float*)d_in[26];
    const float* proj_w2 = (const float*)d_in[27];
    const float* proj_b2 = (const float*)d_in[28];
    float* out = (float*)d_out;
    (void)in_sizes; (void)n_in; (void)out_size;

    float *p_cat1, *p_root;
    __half *p_x16, *p_hxh, *p_wa, *p_wc, *p_zpm, *p_zpa;
    cudaGetSymbolAddress((void**)&p_x16,  g_x16);
    cudaGetSymbolAddress((void**)&p_hxh,  g_hxh);
    cudaGetSymbolAddress((void**)&p_root, g_root);
    cudaGetSymbolAddress((void**)&p_cat1, g_cat1);
    cudaGetSymbolAddress((void**)&p_wa,   g_waT);
    cudaGetSymbolAddress((void**)&p_wc,   g_wcT);
    cudaGetSymbolAddress((void**)&p_zpm,  g_zpm);
    cudaGetSymbolAddress((void**)&p_zpa,  g_zpa);

    constexpr int SMEM3  = 6 * 128 * 40 * 2;    // 61440
    constexpr int SMEML2 = NS * 128 * 4;        // 51200
    cudaFuncSetAttribute(mmagemm<0>, cudaFuncAttributeMaxDynamicSharedMemorySize, SMEM3);
    cudaFuncSetAttribute(mmagemm<1>, cudaFuncAttributeMaxDynamicSharedMemorySize, SMEM3);
    cudaFuncSetAttribute(mmagemm<2>, cudaFuncAttributeMaxDynamicSharedMemorySize, SMEM3);
    cudaFuncSetAttribute(k_tail,     cudaFuncAttributeMaxDynamicSharedMemorySize, SMEML2);

    const int MB = NNP / 128; // 782

    k_wprep<<<(FIN * FIN + 255) / 256, 256>>>(adapter_w, p_wa, FIN, FIN);              // 0
    k_detect<<<1, 32>>>(batch);                                                        // 1
    k_zero<<<(NN + 255) / 256, 256>>>();                                               // 2
    k_xprep<<<(NN * FIN / 8 + 255) / 256, 256>>>(x, p_x16);                            // 3
    k_count<<<(NE + 255) / 256, 256>>>(ei);                                            // 4
    k_alpha<<<(NG + 127) / 128, 128>>>();                                              // 5
    k_wprep<<<(FIN * HIDD + 255) / 256, 256>>>(td1_w, p_wc, FIN, HIDD);
    k_wprep<<<(FIN * HIDD + 255) / 256, 256>>>(bu1_w, p_wc + 128 * FIN, FIN, HIDD);

    // root-gather adapter: g_root = leakyrelu(x_root @ Wa + b)
    mmagemm<0><<<dim3(4, 8), 128, SMEM3>>>(
        p_x16, p_wa, adapter_b, nullptr, nullptr, nullptr, p_root, nullptr, FIN, FIN);

    // prompts on roots + z factors
    k_promptA<<<dim3(NG / 8, 2), 128>>>(p1_w1, p1_b1, p2_w1, p2_b1);
    k_promptLN<<<dim3(NG, 2), 128>>>(p1_lnw, p1_lnb, p2_lnw, p2_lnb);
    k_promptB<<<dim3(NG / 8, 2), 512>>>(p1_w2, p1_b2, p2_w2, p2_b2);
    k_zprep<<<(NG * FIN + 255) / 256, 256>>>(p_zpm, p_zpa);

    // main adapter with fused z epilogue -> A_z (fp16)
    mmagemm<1><<<dim3(4, MB), 128, SMEM3>>>(
        p_x16, p_wa, adapter_b, p_zpm, p_zpa, p_hxh, nullptr, nullptr, FIN, FIN);

    // GCN layer 1 linear (td|bu concat, N=256)
    mmagemm<2><<<dim3(2, MB), 128, SMEM3>>>(
        p_hxh, p_wc, nullptr, nullptr, nullptr, nullptr, nullptr, p_cat1, 256, FIN);

    // fused tail: layer2 + small + projA + projB
    k_tail<<<NG, 256, SMEML2>>>(td1_b, bu1_b, td2_w, td2_b, bu2_w, bu2_b,
                                proj_w1, proj_b1, proj_w2, proj_b2, out);
}

// round 15
// speedup vs baseline: 1.0080x; 1.0080x over previous
#include <cuda_runtime.h>
#include <cuda_fp16.h>
#include <math.h>
#include <stdint.h>

#define NN   100000
#define NNP  100096      // 782 * 128
#define NG   1000
#define NS   100
#define NE   99000
#define FIN  512
#define HIDD 128
#define FO   64

// ---------------- scratch (device globals; no allocations allowed) ----------------
__device__ __align__(16) __half g_x16[NNP * FIN];               // x in fp16 (rows >= NN stay 0)
__device__ __align__(16) __half g_hxh[NNP * FIN];               // A_z fp16
__device__ __align__(16) float g_root[NG * FIN];                // fp32 root hx rows
__device__ __align__(16) float g_cat1[NNP * 256];               // [td1 | bu1] GEMM output
__device__ __align__(16) __half g_waT[FIN * FIN];
__device__ __align__(16) __half g_wcT[256 * FIN];
__device__ __align__(16) __half g_zpm[NG * FIN];
__device__ __align__(16) __half g_zpa[NG * FIN];
__device__ __align__(16) float g_tp[2 * NG * HIDD];
__device__ __align__(16) float g_tln[2 * NG * HIDD];
__device__ __align__(16) float g_pm[2 * NG * FIN];
__device__ __align__(16) float g_alpha[NG];
__device__ __align__(16) float g_stats[4];
__device__ __align__(16) int   g_cnt[NN];
__device__ __align__(16) int   g_parent[NN];
__device__ int   g_idx64;

// ---------------- helpers ----------------
static __device__ __forceinline__ uint32_t smem_u32(const void* p) {
    uint32_t a;
    asm("{ .reg .u64 t; cvta.to.shared.u64 t, %1; cvt.u32.u64 %0, t; }" : "=r"(a) : "l"(p));
    return a;
}
#define CP_ASYNC16(dst_u32, src) \
    asm volatile("cp.async.cg.shared.global [%0], [%1], 16;" :: "r"(dst_u32), "l"(src))
#define CP_COMMIT() asm volatile("cp.async.commit_group;" ::: "memory")
#define CP_WAIT1()  asm volatile("cp.async.wait_group 1;" ::: "memory")

#define MMA_F16(d, a, b0, b1) \
    asm volatile("mma.sync.aligned.m16n8k16.row.col.f32.f16.f16.f32 " \
        "{%0,%1,%2,%3}, {%4,%5,%6,%7}, {%8,%9}, {%0,%1,%2,%3};" \
        : "+f"((d)[0]), "+f"((d)[1]), "+f"((d)[2]), "+f"((d)[3]) \
        : "r"((a)[0]), "r"((a)[1]), "r"((a)[2]), "r"((a)[3]), "r"(b0), "r"(b1))

#define LDSM_X4(r, addr) \
    asm volatile("ldmatrix.sync.aligned.m8n8.x4.shared.b16 {%0,%1,%2,%3}, [%4];" \
        : "=r"((r)[0]), "=r"((r)[1]), "=r"((r)[2]), "=r"((r)[3]) : "r"(addr))

// ---------------- index dtype probe + edge accessors ----------------
__global__ void k_detect(const int* batch) {
    if (threadIdx.x == 0) g_idx64 = (batch[150] == 1) ? 0 : 1;
}
__device__ __forceinline__ int esrc(const void* ei, int e) {
    return g_idx64 ? (int)((const long long*)ei)[e] : ((const int*)ei)[e];
}
__device__ __forceinline__ int edst(const void* ei, int e) {
    return g_idx64 ? (int)((const long long*)ei)[NE + e] : ((const int*)ei)[NE + e];
}

// ---------------- small graph kernels ----------------
__global__ void k_zero() {
    int i = blockIdx.x * blockDim.x + threadIdx.x;
    if (i < NN) g_cnt[i] = 0;
    if (i < 4) g_stats[i] = 0.f;
}
__global__ void k_count(const void* ei) {
    int e = blockIdx.x * blockDim.x + threadIdx.x;
    if (e >= NE) return;
    int s = esrc(ei, e), d = edst(ei, e);
    atomicAdd(&g_cnt[s], 1);
    g_parent[d] = s;
}
__global__ void k_alpha() {
    int g = blockIdx.x * blockDim.x + threadIdx.x;
    if (g >= NG) return;
    float cnt = (float)g_cnt[g * NS];
    float t = (cnt / (float)NS - 0.3f) / 0.1f;
    g_alpha[g] = 1.f / (1.f + expf(-t));
}

// ---------------- preps ----------------
__global__ void k_wprep(const float* __restrict__ w, __half* __restrict__ hi, int K, int Nw) {
    int i = blockIdx.x * blockDim.x + threadIdx.x;
    if (i >= K * Nw) return;
    int k = i / Nw, n = i % Nw;
    hi[(size_t)n * K + k] = __float2half(w[i]);
}
__global__ void k_xprep(const float* __restrict__ x, __half* __restrict__ x16) {
    int i = blockIdx.x * blockDim.x + threadIdx.x;   // over NN*FIN/8
    if (i >= NN * FIN / 8) return;
    float4 a = ((const float4*)x)[i * 2];
    float4 b = ((const float4*)x)[i * 2 + 1];
    union { __half h[8]; uint4 u; } H;
    H.h[0] = __float2half(a.x); H.h[1] = __float2half(a.y);
    H.h[2] = __float2half(a.z); H.h[3] = __float2half(a.w);
    H.h[4] = __float2half(b.x); H.h[5] = __float2half(b.y);
    H.h[6] = __float2half(b.z); H.h[7] = __float2half(b.w);
    ((uint4*)x16)[i] = H.u;
}
__global__ void k_zprep(__half* __restrict__ zpm, __half* __restrict__ zpa) {
    int i = blockIdx.x * blockDim.x + threadIdx.x;
    if (i >= NG * FIN) return;
    int g = i / FIN;
    float a = g_alpha[g];
    zpm[i] = __float2half((1.f - a) * g_pm[i] + a);
    zpa[i] = __float2half(a * g_pm[NG * FIN + i]);
}

// ---------------- HMMA GEMM, fp16, 8 warps (4x2), 3-stage, 1 barrier/iter ----
// (round-13 tiling: warp tile 32x64, MT=2, 256 threads, 2 CTAs/SM = 16 warps/SM)
// MODE 0 (root):    A rows gathered (r -> r*NS); epilogue -> fp32 rootOut (r<NG).
// MODE 1 (adapter): A = x16; epilogue bias+leakyrelu+z -> fp16 Ch.
// MODE 2 (gemm1):   A = A_z; fp32 C epilogue.
template <int MODE>
__global__ void __launch_bounds__(256, 2) mmagemm(
    const __half* __restrict__ Asrc, const __half* __restrict__ Bh,
    const float* __restrict__ bias,
    const __half* __restrict__ zpm, const __half* __restrict__ zpa,
    __half* __restrict__ Ch, float* __restrict__ rootOut, float* __restrict__ C,
    int Ntot, int K)
{
    constexpr int ASZ = 128 * 40;       // elems per stage buffer (10240 B)
    extern __shared__ __align__(16) __half sm[];
    __half* sA = sm;                           // [0, 30720): 3 stages
    __half* sB = sm + 3 * ASZ;                 // [30720, 61440): 3 stages

    const int tid = threadIdx.x, lane = tid & 31, w = tid >> 5;
    const int m0 = blockIdx.y * 128, n0 = blockIdx.x * 128;
    const int warpM = (w & 3) * 32;
    const int warpN = (w >> 2) * 64;
    const int r4 = lane >> 2, q = lane & 3;

    float acc[2][8][4];
#pragma unroll
    for (int mt = 0; mt < 2; mt++)
#pragma unroll
        for (int nt = 0; nt < 8; nt++)
#pragma unroll
            for (int i = 0; i < 4; i++) acc[mt][nt][i] = 0.f;

    const int KS = K >> 5;

    auto stage = [&](int ks, int s) {
#pragma unroll
        for (int c = tid; c < 512; c += 256) {     // A tile: 128 rows x 4 chunks
            int r = c >> 2, qq = c & 3;
            int srow = (MODE == 0) ? min(m0 + r, NG - 1) * NS : (m0 + r);
            const __half* src = Asrc + (size_t)srow * K + ks * 32 + qq * 8;
            CP_ASYNC16(smem_u32(sA + s * ASZ + r * 40) + qq * 16, src);
        }
#pragma unroll
        for (int c = tid; c < 512; c += 256) {     // B tile
            int r = c >> 2, qq = c & 3;
            const __half* src = Bh + (size_t)(n0 + r) * K + ks * 32 + qq * 8;
            CP_ASYNC16(smem_u32(sB + s * ASZ + r * 40) + qq * 16, src);
        }
    };

    // ldmatrix per-lane base addresses
    const int mat = lane >> 3, mrow = lane & 7;
    const uint32_t smb = smem_u32(sm);
    const uint32_t aBase = smb + (uint32_t)((warpM + (mat & 1) * 8 + mrow) * 80 + (mat >> 1) * 16);
    const uint32_t bBase = smb + 30720u + (uint32_t)((warpN + (mat & 1) * 8 + mrow) * 80 + (mat >> 1) * 16);

    // ---- prologue ----
    stage(0, 0); CP_COMMIT();
    stage(1, 1); CP_COMMIT();
    CP_WAIT1();
    __syncthreads();

    for (int ks = 0; ks < KS; ks++) {
        const int s = ks % 3;
        const bool pre = (ks + 2 < KS);
        if (pre) {
            stage(ks + 2, (ks + 2) % 3);
            CP_COMMIT();
        } else {
            CP_COMMIT();
        }

        const uint32_t aS = aBase + (uint32_t)s * 10240u;
        const uint32_t bS = bBase + (uint32_t)s * 10240u;
#pragma unroll
        for (int k16 = 0; k16 < 2; k16++) {
            uint32_t ah[2][4];
            LDSM_X4(ah[0], aS + k16 * 32u);
            LDSM_X4(ah[1], aS + 1280u + k16 * 32u);
            uint32_t bp[2][4];
            LDSM_X4(bp[0], bS + k16 * 32u);
#pragma unroll
            for (int nn = 0; nn < 4; nn++) {       // B fragment ping-pong
                const int cur = nn & 1;
                if (nn < 3) LDSM_X4(bp[cur ^ 1], bS + (nn + 1) * 1280u + k16 * 32u);
#pragma unroll
                for (int e = 0; e < 2; e++) {
                    const int nt = 2 * nn + e;
                    MMA_F16(acc[0][nt], ah[0], bp[cur][e], bp[cur][e + 2]);
                    MMA_F16(acc[1][nt], ah[1], bp[cur][e], bp[cur][e + 2]);
                }
            }
        }
        CP_WAIT1();
        __syncthreads();
    }

    // ---- epilogue ----
#pragma unroll
    for (int mt = 0; mt < 2; mt++) {
#pragma unroll
        for (int nt = 0; nt < 8; nt++) {
            int row = m0 + warpM + mt * 16 + r4;
            int col = n0 + warpN + nt * 8 + q * 2;
            float v0 = acc[mt][nt][0], v1 = acc[mt][nt][1];
            float v2 = acc[mt][nt][2], v3 = acc[mt][nt][3];
            if (MODE == 0) {
                float b0 = bias[col], b1 = bias[col + 1];
                v0 += b0; v1 += b1; v2 += b0; v3 += b1;
                v0 = v0 > 0.f ? v0 : 0.01f * v0;
                v1 = v1 > 0.f ? v1 : 0.01f * v1;
                v2 = v2 > 0.f ? v2 : 0.01f * v2;
                v3 = v3 > 0.f ? v3 : 0.01f * v3;
                if (row < NG)
                    *(float2*)(rootOut + (size_t)row * FIN + col) = make_float2(v0, v1);
                if (row + 8 < NG)
                    *(float2*)(rootOut + (size_t)(row + 8) * FIN + col) = make_float2(v2, v3);
            } else if (MODE == 1) {
                float b0 = bias[col], b1 = bias[col + 1];
                v0 += b0; v1 += b1; v2 += b0; v3 += b1;
                v0 = v0 > 0.f ? v0 : 0.01f * v0;
                v1 = v1 > 0.f ? v1 : 0.01f * v1;
                v2 = v2 > 0.f ? v2 : 0.01f * v2;
                v3 = v3 > 0.f ? v3 : 0.01f * v3;
                int ga = row / NS, gb2 = (row + 8) / NS;
                float2 fm0 = __half22float2(*(const __half2*)(zpm + (size_t)ga * FIN + col));
                float2 fa0 = __half22float2(*(const __half2*)(zpa + (size_t)ga * FIN + col));
                float2 fm1 = __half22float2(*(const __half2*)(zpm + (size_t)gb2 * FIN + col));
                float2 fa1 = __half22float2(*(const __half2*)(zpa + (size_t)gb2 * FIN + col));
                v0 = v0 * fm0.x + fa0.x; v1 = v1 * fm0.y + fa0.y;
                v2 = v2 * fm1.x + fa1.x; v3 = v3 * fm1.y + fa1.y;
                *(__half2*)(Ch + (size_t)row * Ntot + col) = __floats2half2_rn(v0, v1);
                *(__half2*)(Ch + (size_t)(row + 8) * Ntot + col) = __floats2half2_rn(v2, v3);
            } else {
                *(float2*)(C + (size_t)row * Ntot + col) = make_float2(v0, v1);
                *(float2*)(C + (size_t)(row + 8) * Ntot + col) = make_float2(v2, v3);
            }
        }
    }
}

// ---------------- prompt kernels (8 graphs per block) ----------------
__global__ void k_promptA(const float* __restrict__ w1a, const float* __restrict__ b1a,
                          const float* __restrict__ w1b, const float* __restrict__ b1b) {
    const int gb = blockIdx.x * 8, which = blockIdx.y, j = threadIdx.x;  // 128 threads
    const float* w = which ? w1b : w1a;
    const float* b = which ? b1b : b1a;
    __shared__ float rfs[8 * 128];
    float acc[8];
    float bj = b[j];
#pragma unroll
    for (int g = 0; g < 8; g++) acc[g] = bj;
    for (int kc = 0; kc < 4; kc++) {
        __syncthreads();
#pragma unroll
        for (int idx = j; idx < 1024; idx += 128) {
            int g = idx >> 7, k = idx & 127;
            rfs[idx] = g_root[(size_t)(gb + g) * FIN + kc * 128 + k];
        }
        __syncthreads();
#pragma unroll 2
        for (int k = 0; k < 128; k++) {
            float wv = w[(kc * 128 + k) * HIDD + j];
#pragma unroll
            for (int g = 0; g < 8; g++)
                acc[g] = fmaf(rfs[g * 128 + k], wv, acc[g]);
        }
    }
    float l1 = 0.f, l2 = 0.f;
#pragma unroll
    for (int g = 0; g < 8; g++) {
        g_tp[which * NG * HIDD + (gb + g) * HIDD + j] = acc[g];
        l1 += acc[g];
        l2 += acc[g] * acc[g];
    }
    __shared__ float s1[128], s2[128];
    s1[j] = l1; s2[j] = l2;
    __syncthreads();
    for (int o = 64; o > 0; o >>= 1) {
        if (j < o) { s1[j] += s1[j + o]; s2[j] += s2[j + o]; }
        __syncthreads();
    }
    if (j == 0) {
        atomicAdd(&g_stats[which * 2 + 0], s1[0]);
        atomicAdd(&g_stats[which * 2 + 1], s2[0]);
    }
}
__global__ void k_promptLN(const float* __restrict__ lnwa, const float* __restrict__ lnba,
                           const float* __restrict__ lnwb, const float* __restrict__ lnbb) {
    int g = blockIdx.x, which = blockIdx.y, j = threadIdx.x;
    const float* lw = which ? lnwb : lnwa;
    const float* lb = which ? lnbb : lnba;
    const float inv_n = 1.f / (float)(NG * HIDD);
    float m = g_stats[which * 2 + 0] * inv_n;
    float msq = fmaxf(g_stats[which * 2 + 1] * inv_n - m * m, 0.f);
    float denom = sqrtf(msq) + 1e-5f;
    float t = g_tp[which * NG * HIDD + g * HIDD + j];
    float v = (t - m) / denom * lw[j] + lb[j];
    g_tln[which * NG * HIDD + g * HIDD + j] = tanhf(v);
}
__global__ void k_promptB(const float* __restrict__ w2a, const float* __restrict__ b2a,
                          const float* __restrict__ w2b, const float* __restrict__ b2b) {
    const int gb = blockIdx.x * 8, which = blockIdx.y, j = threadIdx.x;  // 512 threads
    const float* w = which ? w2b : w2a;
    const float* b = which ? b2b : b2a;
    __shared__ float ts[8 * 128];
#pragma unroll
    for (int idx = j; idx < 1024; idx += 512) {
        int g = idx >> 7, k = idx & 127;
        ts[idx] = g_tln[which * NG * HIDD + (gb + g) * HIDD + k];
    }
    __syncthreads();
    float acc[8];
    float bj = b[j];
#pragma unroll
    for (int g = 0; g < 8; g++) acc[g] = bj;
#pragma unroll 2
    for (int k = 0; k < 128; k++) {
        float wv = w[k * FIN + j];
#pragma unroll
        for (int g = 0; g < 8; g++)
            acc[g] = fmaf(ts[g * 128 + k], wv, acc[g]);
    }
#pragma unroll
    for (int g = 0; g < 8; g++)
        g_pm[which * NG * FIN + (gb + g) * FIN + j] = acc[g];
}

// ---------------- fused tail: layer2 + small GEMM + projA + projB ----------------
__global__ void k_tail(const float* __restrict__ td1_b, const float* __restrict__ bu1_b,
                       const float* __restrict__ w2td, const float* __restrict__ td2_b,
                       const float* __restrict__ w2bu, const float* __restrict__ bu2_b,
                       const float* __restrict__ pw1, const float* __restrict__ pb1,
                       const float* __restrict__ pw2, const float* __restrict__ pb2,
                       float* __restrict__ out) {
    extern __shared__ float buacc[];            // [NS][128]
    __shared__ float dinvb[NS], cntS[NS];
    __shared__ int   pl[NS];
    __shared__ float sS[256];                   // [s_td | s_bu]
    __shared__ float hc[128];                   // hcat
    __shared__ float r1s[256];
    const int g = blockIdx.x, t = threadIdx.x;  // 256 threads
    for (int n = t; n < NS; n += 256) {
        int i = g * NS + n;
        int c = g_cnt[i];
        cntS[n]  = (float)c;
        dinvb[n] = rsqrtf((float)(c + 1));
        pl[n]    = n ? (g_parent[i] - g * NS) : 0;
    }
    __syncthreads();
    // ---- phase 1: layer-1 aggregation + layer-2 collapse ----
    if (t < 128) {
        const int f = t;
        const float btd = td1_b[f];
        float s_td = 0.f;
        for (int n = 0; n < NS; n++) {
            float utd = g_cat1[(size_t)(g * NS + n) * 256 + f];
            float v, c_td;
            if (n) {
                int p = pl[n];
                float dp = p ? 0.70710678118654752f : 1.0f;
                float up = g_cat1[(size_t)(g * NS + p) * 256 + f];
                v = utd * 0.5f + up * dp * 0.70710678118654752f + btd;
                c_td = 0.5f + 0.5f * cntS[n];
            } else {
                v = utd + btd;
                c_td = 1.0f + 0.70710678118654752f * cntS[0];
            }
            v = v > 0.f ? v : 0.f;
            s_td += c_td * v;
        }
        sS[f] = s_td;
    } else {
        const int f = t - 128;
        const float bbu = bu1_b[f];
        for (int n = 0; n < NS; n++) {
            float ubu = g_cat1[(size_t)(g * NS + n) * 256 + 128 + f];
            float db = dinvb[n];
            if (n) {
                buacc[pl[n] * 128 + f] += ubu * db * dinvb[pl[n]];
                buacc[n * 128 + f] = ubu * db * db;
            } else {
                buacc[f] = ubu * db * db;
            }
        }
        float s_bu = 0.f;
        for (int n = 0; n < NS; n++) {
            float v = buacc[n * 128 + f] + bbu;
            v = v > 0.f ? v : 0.f;
            float db = dinvb[n];
            float c_bu = db * db + (n ? db * dinvb[pl[n]] : 0.f);
            s_bu += c_bu * v;
        }
        sS[128 + f] = s_bu;
    }
    __syncthreads();
    // ---- phase 2: small layer-2 GEMM -> hc ----
    if (t < 128) {
        float acc;
        if (t < FO) {
            acc = (float)NS * bu2_b[t];
#pragma unroll 4
            for (int k = 0; k < HIDD; k++) acc = fmaf(sS[128 + k], w2bu[k * FO + t], acc);
        } else {
            int jj = t - FO;
            acc = (float)NS * td2_b[jj];
#pragma unroll 4
            for (int k = 0; k < HIDD; k++) acc = fmaf(sS[k], w2td[k * FO + jj], acc);
        }
        hc[t] = acc;
    }
    __syncthreads();
    // ---- phase 3: projA -> r1s ----
    {
        float acc = pb1[t];
#pragma unroll 4
        for (int k = 0; k < 128; k++) acc = fmaf(hc[k], pw1[k * 256 + t], acc);
        r1s[t] = acc > 0.f ? acc : 0.f;
    }
    __syncthreads();
    // ---- phase 4: projB -> out ----
    if (t < 128) {
        float acc = pb2[t];
#pragma unroll 4
        for (int k = 0; k < 256; k++) acc = fmaf(r1s[k], pw2[k * 128 + t], acc);
        out[g * 128 + t] = acc;
    }
}

// ---------------- launch ----------------
extern "C" void kernel_launch(void* const* d_in, const int* in_sizes, int n_in,
                              void* d_out, int out_size) {
    const float* x         = (const float*)d_in[0];
    const void*  ei        = d_in[1];
    const int*   batch     = (const int*)d_in[2];
    const float* adapter_w = (const float*)d_in[3];
    const float* adapter_b = (const float*)d_in[4];
    const float* p1_w1 = (const float*)d_in[5];
    const float* p1_b1 = (const float*)d_in[6];
    const float* p1_lnw = (const float*)d_in[7];
    const float* p1_lnb = (const float*)d_in[8];
    const float* p1_w2 = (const float*)d_in[9];
    const float* p1_b2 = (const float*)d_in[10];
    const float* p2_w1 = (const float*)d_in[11];
    const float* p2_b1 = (const float*)d_in[12];
    const float* p2_lnw = (const float*)d_in[13];
    const float* p2_lnb = (const float*)d_in[14];
    const float* p2_w2 = (const float*)d_in[15];
    const float* p2_b2 = (const float*)d_in[16];
    const float* td1_w = (const float*)d_in[17];
    const float* td1_b = (const float*)d_in[18];
    const float* td2_w = (const float*)d_in[19];
    const float* td2_b = (const float*)d_in[20];
    const float* bu1_w = (const float*)d_in[21];
    const float* bu1_b = (const float*)d_in[22];
    const float* bu2_w = (const float*)d_in[23];
    const float* bu2_b = (const float*)d_in[24];
    const float* proj_w1 = (const float*)d_in[25];
    const float* proj_b1 = (const float*)d_in[26];
    const float* proj_w2 = (const float*)d_in[27];
    const float* proj_b2 = (const float*)d_in[28];
    float* out = (float*)d_out;
    (void)in_sizes; (void)n_in; (void)out_size;

    float *p_cat1, *p_root;
    __half *p_x16, *p_hxh, *p_wa, *p_wc, *p_zpm, *p_zpa;
    cudaGetSymbolAddress((void**)&p_x16,  g_x16);
    cudaGetSymbolAddress((void**)&p_hxh,  g_hxh);
    cudaGetSymbolAddress((void**)&p_root, g_root);
    cudaGetSymbolAddress((void**)&p_cat1, g_cat1);
    cudaGetSymbolAddress((void**)&p_wa,   g_waT);
    cudaGetSymbolAddress((void**)&p_wc,   g_wcT);
    cudaGetSymbolAddress((void**)&p_zpm,  g_zpm);
    cudaGetSymbolAddress((void**)&p_zpa,  g_zpa);

    constexpr int SMEM3  = 6 * 128 * 40 * 2;    // 61440
    constexpr int SMEML2 = NS * 128 * 4;        // 51200
    cudaFuncSetAttribute(mmagemm<0>, cudaFuncAttributeMaxDynamicSharedMemorySize, SMEM3);
    cudaFuncSetAttribute(mmagemm<1>, cudaFuncAttributeMaxDynamicSharedMemorySize, SMEM3);
    cudaFuncSetAttribute(mmagemm<2>, cudaFuncAttributeMaxDynamicSharedMemorySize, SMEM3);
    cudaFuncSetAttribute(k_tail,     cudaFuncAttributeMaxDynamicSharedMemorySize, SMEML2);

    const int MB = NNP / 128; // 782

    k_wprep<<<(FIN * FIN + 255) / 256, 256>>>(adapter_w, p_wa, FIN, FIN);              // 0
    k_detect<<<1, 32>>>(batch);                                                        // 1
    k_zero<<<(NN + 255) / 256, 256>>>();                                               // 2
    k_xprep<<<(NN * FIN / 8 + 255) / 256, 256>>>(x, p_x16);                            // 3
    k_count<<<(NE + 255) / 256, 256>>>(ei);                                            // 4
    k_alpha<<<(NG + 127) / 128, 128>>>();                                              // 5
    k_wprep<<<(FIN * HIDD + 255) / 256, 256>>>(td1_w, p_wc, FIN, HIDD);
    k_wprep<<<(FIN * HIDD + 255) / 256, 256>>>(bu1_w, p_wc + 128 * FIN, FIN, HIDD);

    // root-gather adapter: g_root = leakyrelu(x_root @ Wa + b)
    mmagemm<0><<<dim3(4, 8), 256, SMEM3>>>(
        p_x16, p_wa, adapter_b, nullptr, nullptr, nullptr, p_root, nullptr, FIN, FIN);

    // prompts on roots + z factors
    k_promptA<<<dim3(NG / 8, 2), 128>>>(p1_w1, p1_b1, p2_w1, p2_b1);
    k_promptLN<<<dim3(NG, 2), 128>>>(p1_lnw, p1_lnb, p2_lnw, p2_lnb);
    k_promptB<<<dim3(NG / 8, 2), 512>>>(p1_w2, p1_b2, p2_w2, p2_b2);
    k_zprep<<<(NG * FIN + 255) / 256, 256>>>(p_zpm, p_zpa);

    // main adapter with fused z epilogue -> A_z (fp16)
    mmagemm<1><<<dim3(4, MB), 256, SMEM3>>>(
        p_x16, p_wa, adapter_b, p_zpm, p_zpa, p_hxh, nullptr, nullptr, FIN, FIN);

    // GCN layer 1 linear (td|bu concat, N=256)
    mmagemm<2><<<dim3(2, MB), 256, SMEM3>>>(
        p_hxh, p_wc, nullptr, nullptr, nullptr, nullptr, nullptr, p_cat1, 256, FIN);

    // fused tail: layer2 + small + projA + projB
    k_tail<<<NG, 256, SMEML2>>>(td1_b, bu1_b, td2_w, td2_b, bu2_w, bu2_b,
                                proj_w1, proj_b1, proj_w2, proj_b2, out);
}

// round 16
// speedup vs baseline: 1.1449x; 1.1359x over previous
#include <cuda_runtime.h>
#include <cuda_fp16.h>
#include <math.h>
#include <stdint.h>

#define NN   100000
#define NNP  100096      // 782 * 128
#define NG   1000
#define NS   100
#define NE   99000
#define FIN  512
#define HIDD 128
#define FO   64

// ---------------- scratch (device globals; no allocations allowed) ----------------
__device__ __align__(16) __half g_x16[NNP * FIN];               // x in fp16 (rows >= NN stay 0)
__device__ __align__(16) __half g_hxh[NNP * FIN];               // A_z fp16
__device__ __align__(16) float g_root[NG * FIN];                // fp32 root hx rows
__device__ __align__(16) __half g_cat1[NNP * 256];              // [td1 | bu1] GEMM output (fp16)
__device__ __align__(16) __half g_waT[FIN * FIN];
__device__ __align__(16) __half g_wcT[256 * FIN];
__device__ __align__(16) __half g_zpm[NG * FIN];
__device__ __align__(16) __half g_zpa[NG * FIN];
__device__ __align__(16) float g_tp[2 * NG * HIDD];
__device__ __align__(16) float g_tln[2 * NG * HIDD];
__device__ __align__(16) float g_pm[2 * NG * FIN];
__device__ __align__(16) float g_s[NG * 256];                   // [s_td | s_bu] per graph
__device__ __align__(16) float g_hcat[NG * 128];
__device__ __align__(16) float g_r1[NG * 256];
__device__ __align__(16) float g_alpha[NG];
__device__ __align__(16) float g_stats[4];
__device__ __align__(16) int   g_cnt[NN];
__device__ __align__(16) int   g_parent[NN];
__device__ int   g_idx64;

// ---------------- helpers ----------------
static __device__ __forceinline__ uint32_t smem_u32(const void* p) {
    uint32_t a;
    asm("{ .reg .u64 t; cvta.to.shared.u64 t, %1; cvt.u32.u64 %0, t; }" : "=r"(a) : "l"(p));
    return a;
}
#define CP_ASYNC16(dst_u32, src) \
    asm volatile("cp.async.cg.shared.global [%0], [%1], 16;" :: "r"(dst_u32), "l"(src))
#define CP_COMMIT() asm volatile("cp.async.commit_group;" ::: "memory")
#define CP_WAIT1()  asm volatile("cp.async.wait_group 1;" ::: "memory")

#define MMA_F16(d, a, b0, b1) \
    asm volatile("mma.sync.aligned.m16n8k16.row.col.f32.f16.f16.f32 " \
        "{%0,%1,%2,%3}, {%4,%5,%6,%7}, {%8,%9}, {%0,%1,%2,%3};" \
        : "+f"((d)[0]), "+f"((d)[1]), "+f"((d)[2]), "+f"((d)[3]) \
        : "r"((a)[0]), "r"((a)[1]), "r"((a)[2]), "r"((a)[3]), "r"(b0), "r"(b1))

#define LDSM_X4(r, addr) \
    asm volatile("ldmatrix.sync.aligned.m8n8.x4.shared.b16 {%0,%1,%2,%3}, [%4];" \
        : "=r"((r)[0]), "=r"((r)[1]), "=r"((r)[2]), "=r"((r)[3]) : "r"(addr))

// ---------------- index dtype probe + edge accessors ----------------
__global__ void k_detect(const int* batch) {
    if (threadIdx.x == 0) g_idx64 = (batch[150] == 1) ? 0 : 1;
}
__device__ __forceinline__ int esrc(const void* ei, int e) {
    return g_idx64 ? (int)((const long long*)ei)[e] : ((const int*)ei)[e];
}
__device__ __forceinline__ int edst(const void* ei, int e) {
    return g_idx64 ? (int)((const long long*)ei)[NE + e] : ((const int*)ei)[NE + e];
}

// ---------------- small graph kernels ----------------
__global__ void k_zero() {
    int i = blockIdx.x * blockDim.x + threadIdx.x;
    if (i < NN) g_cnt[i] = 0;
    if (i < 4) g_stats[i] = 0.f;
}
__global__ void k_count(const void* ei) {
    int e = blockIdx.x * blockDim.x + threadIdx.x;
    if (e >= NE) return;
    int s = esrc(ei, e), d = edst(ei, e);
    atomicAdd(&g_cnt[s], 1);
    g_parent[d] = s;
}
__global__ void k_alpha() {
    int g = blockIdx.x * blockDim.x + threadIdx.x;
    if (g >= NG) return;
    float cnt = (float)g_cnt[g * NS];
    float t = (cnt / (float)NS - 0.3f) / 0.1f;
    g_alpha[g] = 1.f / (1.f + expf(-t));
}

// ---------------- preps ----------------
__global__ void k_wprep(const float* __restrict__ w, __half* __restrict__ hi, int K, int Nw) {
    int i = blockIdx.x * blockDim.x + threadIdx.x;
    if (i >= K * Nw) return;
    int k = i / Nw, n = i % Nw;
    hi[(size_t)n * K + k] = __float2half(w[i]);
}
__global__ void k_xprep(const float* __restrict__ x, __half* __restrict__ x16) {
    int i = blockIdx.x * blockDim.x + threadIdx.x;   // over NN*FIN/8
    if (i >= NN * FIN / 8) return;
    float4 a = ((const float4*)x)[i * 2];
    float4 b = ((const float4*)x)[i * 2 + 1];
    union { __half h[8]; uint4 u; } H;
    H.h[0] = __float2half(a.x); H.h[1] = __float2half(a.y);
    H.h[2] = __float2half(a.z); H.h[3] = __float2half(a.w);
    H.h[4] = __float2half(b.x); H.h[5] = __float2half(b.y);
    H.h[6] = __float2half(b.z); H.h[7] = __float2half(b.w);
    ((uint4*)x16)[i] = H.u;
}
__global__ void k_zprep(__half* __restrict__ zpm, __half* __restrict__ zpa) {
    int i = blockIdx.x * blockDim.x + threadIdx.x;
    if (i >= NG * FIN) return;
    int g = i / FIN;
    float a = g_alpha[g];
    zpm[i] = __float2half((1.f - a) * g_pm[i] + a);
    zpa[i] = __float2half(a * g_pm[NG * FIN + i]);
}

// ---------------- HMMA GEMM, fp16, 8 warps (4x2), 3-stage, 1 barrier/iter ----
// MODE 0 (root):    A rows gathered (r -> r*NS); epilogue -> fp32 rootOut (r<NG).
// MODE 1 (adapter): A = x16; epilogue bias+leakyrelu+z -> fp16 Ch.
// MODE 2 (gemm1):   A = A_z; fp16 Ch epilogue (cat1).
template <int MODE>
__global__ void __launch_bounds__(256, 2) mmagemm(
    const __half* __restrict__ Asrc, const __half* __restrict__ Bh,
    const float* __restrict__ bias,
    const __half* __restrict__ zpm, const __half* __restrict__ zpa,
    __half* __restrict__ Ch, float* __restrict__ rootOut,
    int Ntot, int K)
{
    constexpr int ASZ = 128 * 40;       // elems per stage buffer (10240 B)
    extern __shared__ __align__(16) __half sm[];
    __half* sA = sm;                           // [0, 30720): 3 stages
    __half* sB = sm + 3 * ASZ;                 // [30720, 61440): 3 stages

    const int tid = threadIdx.x, lane = tid & 31, w = tid >> 5;
    const int m0 = blockIdx.y * 128, n0 = blockIdx.x * 128;
    const int warpM = (w & 3) * 32;
    const int warpN = (w >> 2) * 64;
    const int r4 = lane >> 2, q = lane & 3;

    float acc[2][8][4];
#pragma unroll
    for (int mt = 0; mt < 2; mt++)
#pragma unroll
        for (int nt = 0; nt < 8; nt++)
#pragma unroll
            for (int i = 0; i < 4; i++) acc[mt][nt][i] = 0.f;

    const int KS = K >> 5;

    auto stage = [&](int ks, int s) {
#pragma unroll
        for (int c = tid; c < 512; c += 256) {     // A tile: 128 rows x 4 chunks
            int r = c >> 2, qq = c & 3;
            int srow = (MODE == 0) ? min(m0 + r, NG - 1) * NS : (m0 + r);
            const __half* src = Asrc + (size_t)srow * K + ks * 32 + qq * 8;
            CP_ASYNC16(smem_u32(sA + s * ASZ + r * 40) + qq * 16, src);
        }
#pragma unroll
        for (int c = tid; c < 512; c += 256) {     // B tile
            int r = c >> 2, qq = c & 3;
            const __half* src = Bh + (size_t)(n0 + r) * K + ks * 32 + qq * 8;
            CP_ASYNC16(smem_u32(sB + s * ASZ + r * 40) + qq * 16, src);
        }
    };

    // ldmatrix per-lane base addresses
    const int mat = lane >> 3, mrow = lane & 7;
    const uint32_t smb = smem_u32(sm);
    const uint32_t aBase = smb + (uint32_t)((warpM + (mat & 1) * 8 + mrow) * 80 + (mat >> 1) * 16);
    const uint32_t bBase = smb + 30720u + (uint32_t)((warpN + (mat & 1) * 8 + mrow) * 80 + (mat >> 1) * 16);

    // ---- prologue ----
    stage(0, 0); CP_COMMIT();
    stage(1, 1); CP_COMMIT();
    CP_WAIT1();
    __syncthreads();

    for (int ks = 0; ks < KS; ks++) {
        const int s = ks % 3;
        const bool pre = (ks + 2 < KS);
        if (pre) {
            stage(ks + 2, (ks + 2) % 3);
            CP_COMMIT();
        } else {
            CP_COMMIT();
        }

        const uint32_t aS = aBase + (uint32_t)s * 10240u;
        const uint32_t bS = bBase + (uint32_t)s * 10240u;
#pragma unroll
        for (int k16 = 0; k16 < 2; k16++) {
            uint32_t ah[2][4];
            LDSM_X4(ah[0], aS + k16 * 32u);
            LDSM_X4(ah[1], aS + 1280u + k16 * 32u);
            uint32_t bp[2][4];
            LDSM_X4(bp[0], bS + k16 * 32u);
#pragma unroll
            for (int nn = 0; nn < 4; nn++) {       // B fragment ping-pong
                const int cur = nn & 1;
                if (nn < 3) LDSM_X4(bp[cur ^ 1], bS + (nn + 1) * 1280u + k16 * 32u);
#pragma unroll
                for (int e = 0; e < 2; e++) {
                    const int nt = 2 * nn + e;
                    MMA_F16(acc[0][nt], ah[0], bp[cur][e], bp[cur][e + 2]);
                    MMA_F16(acc[1][nt], ah[1], bp[cur][e], bp[cur][e + 2]);
                }
            }
        }
        CP_WAIT1();
        __syncthreads();
    }

    // ---- epilogue ----
#pragma unroll
    for (int mt = 0; mt < 2; mt++) {
#pragma unroll
        for (int nt = 0; nt < 8; nt++) {
            int row = m0 + warpM + mt * 16 + r4;
            int col = n0 + warpN + nt * 8 + q * 2;
            float v0 = acc[mt][nt][0], v1 = acc[mt][nt][1];
            float v2 = acc[mt][nt][2], v3 = acc[mt][nt][3];
            if (MODE == 0) {
                float b0 = bias[col], b1 = bias[col + 1];
                v0 += b0; v1 += b1; v2 += b0; v3 += b1;
                v0 = v0 > 0.f ? v0 : 0.01f * v0;
                v1 = v1 > 0.f ? v1 : 0.01f * v1;
                v2 = v2 > 0.f ? v2 : 0.01f * v2;
                v3 = v3 > 0.f ? v3 : 0.01f * v3;
                if (row < NG)
                    *(float2*)(rootOut + (size_t)row * FIN + col) = make_float2(v0, v1);
                if (row + 8 < NG)
                    *(float2*)(rootOut + (size_t)(row + 8) * FIN + col) = make_float2(v2, v3);
            } else if (MODE == 1) {
                float b0 = bias[col], b1 = bias[col + 1];
                v0 += b0; v1 += b1; v2 += b0; v3 += b1;
                v0 = v0 > 0.f ? v0 : 0.01f * v0;
                v1 = v1 > 0.f ? v1 : 0.01f * v1;
                v2 = v2 > 0.f ? v2 : 0.01f * v2;
                v3 = v3 > 0.f ? v3 : 0.01f * v3;
                int ga = row / NS, gb2 = (row + 8) / NS;
                float2 fm0 = __half22float2(*(const __half2*)(zpm + (size_t)ga * FIN + col));
                float2 fa0 = __half22float2(*(const __half2*)(zpa + (size_t)ga * FIN + col));
                float2 fm1 = __half22float2(*(const __half2*)(zpm + (size_t)gb2 * FIN + col));
                float2 fa1 = __half22float2(*(const __half2*)(zpa + (size_t)gb2 * FIN + col));
                v0 = v0 * fm0.x + fa0.x; v1 = v1 * fm0.y + fa0.y;
                v2 = v2 * fm1.x + fa1.x; v3 = v3 * fm1.y + fa1.y;
                *(__half2*)(Ch + (size_t)row * Ntot + col) = __floats2half2_rn(v0, v1);
                *(__half2*)(Ch + (size_t)(row + 8) * Ntot + col) = __floats2half2_rn(v2, v3);
            } else {
                *(__half2*)(Ch + (size_t)row * Ntot + col) = __floats2half2_rn(v0, v1);
                *(__half2*)(Ch + (size_t)(row + 8) * Ntot + col) = __floats2half2_rn(v2, v3);
            }
        }
    }
}

// ---------------- prompt kernels (4 graphs per block; round-13 config) ----------------
__global__ void k_promptA(const float* __restrict__ w1a, const float* __restrict__ b1a,
                          const float* __restrict__ w1b, const float* __restrict__ b1b) {
    const int gb = blockIdx.x * 4, which = blockIdx.y, j = threadIdx.x;  // 128 threads
    const float* w = which ? w1b : w1a;
    const float* b = which ? b1b : b1a;
    __shared__ float rfs[4 * 128];
    float acc[4];
    float bj = b[j];
#pragma unroll
    for (int g = 0; g < 4; g++) acc[g] = bj;
    for (int kc = 0; kc < 4; kc++) {
        __syncthreads();
#pragma unroll
        for (int idx = j; idx < 512; idx += 128) {
            int g = idx >> 7, k = idx & 127;
            rfs[idx] = g_root[(size_t)(gb + g) * FIN + kc * 128 + k];
        }
        __syncthreads();
#pragma unroll 4
        for (int k = 0; k < 128; k++) {
            float wv = w[(kc * 128 + k) * HIDD + j];
            acc[0] = fmaf(rfs[k], wv, acc[0]);
            acc[1] = fmaf(rfs[128 + k], wv, acc[1]);
            acc[2] = fmaf(rfs[256 + k], wv, acc[2]);
            acc[3] = fmaf(rfs[384 + k], wv, acc[3]);
        }
    }
    float l1 = 0.f, l2 = 0.f;
#pragma unroll
    for (int g = 0; g < 4; g++) {
        g_tp[which * NG * HIDD + (gb + g) * HIDD + j] = acc[g];
        l1 += acc[g];
        l2 += acc[g] * acc[g];
    }
    __shared__ float s1[128], s2[128];
    s1[j] = l1; s2[j] = l2;
    __syncthreads();
    for (int o = 64; o > 0; o >>= 1) {
        if (j < o) { s1[j] += s1[j + o]; s2[j] += s2[j + o]; }
        __syncthreads();
    }
    if (j == 0) {
        atomicAdd(&g_stats[which * 2 + 0], s1[0]);
        atomicAdd(&g_stats[which * 2 + 1], s2[0]);
    }
}
__global__ void k_promptLN(const float* __restrict__ lnwa, const float* __restrict__ lnba,
                           const float* __restrict__ lnwb, const float* __restrict__ lnbb) {
    int g = blockIdx.x, which = blockIdx.y, j = threadIdx.x;
    const float* lw = which ? lnwb : lnwa;
    const float* lb = which ? lnbb : lnba;
    const float inv_n = 1.f / (float)(NG * HIDD);
    float m = g_stats[which * 2 + 0] * inv_n;
    float msq = fmaxf(g_stats[which * 2 + 1] * inv_n - m * m, 0.f);
    float denom = sqrtf(msq) + 1e-5f;
    float t = g_tp[which * NG * HIDD + g * HIDD + j];
    float v = (t - m) / denom * lw[j] + lb[j];
    g_tln[which * NG * HIDD + g * HIDD + j] = tanhf(v);
}
__global__ void k_promptB(const float* __restrict__ w2a, const float* __restrict__ b2a,
                          const float* __restrict__ w2b, const float* __restrict__ b2b) {
    const int gb = blockIdx.x * 4, which = blockIdx.y, j = threadIdx.x;  // 512 threads
    const float* w = which ? w2b : w2a;
    const float* b = which ? b2b : b2a;
    __shared__ float ts[4 * 128];
    if (j < 512) {
        int g = j >> 7, k = j & 127;
        ts[j] = g_tln[which * NG * HIDD + (gb + g) * HIDD + k];
    }
    __syncthreads();
    float acc[4];
    float bj = b[j];
#pragma unroll
    for (int g = 0; g < 4; g++) acc[g] = bj;
#pragma unroll 4
    for (int k = 0; k < 128; k++) {
        float wv = w[k * FIN + j];
        acc[0] = fmaf(ts[k], wv, acc[0]);
        acc[1] = fmaf(ts[128 + k], wv, acc[1]);
        acc[2] = fmaf(ts[256 + k], wv, acc[2]);
        acc[3] = fmaf(ts[384 + k], wv, acc[3]);
    }
#pragma unroll
    for (int g = 0; g < 4; g++)
        g_pm[which * NG * FIN + (gb + g) * FIN + j] = acc[g];
}

// ---------------- fused layer-1 aggregation + layer-2 collapse (TD/BU concurrent) ----------------
__global__ void k_layer2(const float* __restrict__ td1_b, const float* __restrict__ bu1_b,
                         float* __restrict__ s_out) {
    extern __shared__ float buacc[];            // [NS][128], BU half only
    __shared__ float dinvb[NS], cntS[NS];
    __shared__ int   pl[NS];
    const int g = blockIdx.x, t = threadIdx.x;  // 256 threads
    for (int n = t; n < NS; n += 256) {
        int i = g * NS + n;
        int c = g_cnt[i];
        cntS[n]  = (float)c;
        dinvb[n] = rsqrtf((float)(c + 1));
        pl[n]    = n ? (g_parent[i] - g * NS) : 0;
    }
    __syncthreads();
    if (t < 128) {
        const int f = t;
        const float btd = td1_b[f];
        float s_td = 0.f;
        for (int n = 0; n < NS; n++) {
            float utd = __half2float(g_cat1[(size_t)(g * NS + n) * 256 + f]);
            float v, c_td;
            if (n) {
                int p = pl[n];
                float dp = p ? 0.70710678118654752f : 1.0f;
                float up = __half2float(g_cat1[(size_t)(g * NS + p) * 256 + f]);
                v = utd * 0.5f + up * dp * 0.70710678118654752f + btd;
                c_td = 0.5f + 0.5f * cntS[n];
            } else {
                v = utd + btd;
                c_td = 1.0f + 0.70710678118654752f * cntS[0];
            }
            v = v > 0.f ? v : 0.f;
            s_td += c_td * v;
        }
        s_out[g * 256 + f] = s_td;
    } else {
        const int f = t - 128;
        const float bbu = bu1_b[f];
        for (int n = 0; n < NS; n++) {
            float ubu = __half2float(g_cat1[(size_t)(g * NS + n) * 256 + 128 + f]);
            float db = dinvb[n];
            if (n) {
                buacc[pl[n] * 128 + f] += ubu * db * dinvb[pl[n]];
                buacc[n * 128 + f] = ubu * db * db;
            } else {
                buacc[f] = ubu * db * db;
            }
        }
        float s_bu = 0.f;
        for (int n = 0; n < NS; n++) {
            float v = buacc[n * 128 + f] + bbu;
            v = v > 0.f ? v : 0.f;
            float db = dinvb[n];
            float c_bu = db * db + (n ? db * dinvb[pl[n]] : 0.f);
            s_bu += c_bu * v;
        }
        s_out[g * 256 + 128 + f] = s_bu;
    }
}

// small layer-2 GEMM: hcat = [s_bu @ W2bu + 100*b_bu2 | s_td @ W2td + 100*b_td2]
__global__ void k_small(const float* __restrict__ w2td, const float* __restrict__ td2_b,
                        const float* __restrict__ w2bu, const float* __restrict__ bu2_b) {
    int g = blockIdx.x, j = threadIdx.x;  // 128 threads
    __shared__ float sh[256];
    sh[j] = g_s[g * 256 + j];
    sh[j + 128] = g_s[g * 256 + 128 + j];
    __syncthreads();
    float acc;
    if (j < FO) {
        acc = (float)NS * bu2_b[j];
#pragma unroll 4
        for (int k = 0; k < HIDD; k++) acc = fmaf(sh[128 + k], w2bu[k * FO + j], acc);
        g_hcat[g * 128 + j] = acc;
    } else {
        int jj = j - FO;
        acc = (float)NS * td2_b[jj];
#pragma unroll 4
        for (int k = 0; k < HIDD; k++) acc = fmaf(sh[k], w2td[k * FO + jj], acc);
        g_hcat[g * 128 + j] = acc;
    }
}

// ---------------- final projection ----------------
__global__ void k_projA(const float* __restrict__ w1, const float* __restrict__ b1) {
    int g = blockIdx.x, j = threadIdx.x; // 256 threads
    __shared__ float sh[128];
    if (j < 128) sh[j] = g_hcat[g * 128 + j];
    __syncthreads();
    float acc = b1[j];
#pragma unroll 4
    for (int k = 0; k < 128; k++) acc = fmaf(sh[k], w1[k * 256 + j], acc);
    g_r1[g * 256 + j] = acc > 0.f ? acc : 0.f;
}
__global__ void k_projB(const float* __restrict__ w2, const float* __restrict__ b2,
                        float* __restrict__ out) {
    int g = blockIdx.x, j = threadIdx.x; // 128 threads
    __shared__ float sh[256];
    sh[j] = g_r1[g * 256 + j];
    sh[j + 128] = g_r1[g * 256 + 128 + j];
    __syncthreads();
    float acc = b2[j];
#pragma unroll 4
    for (int k = 0; k < 256; k++) acc = fmaf(sh[k], w2[k * 128 + j], acc);
    out[g * 128 + j] = acc;
}

// ---------------- launch ----------------
extern "C" void kernel_launch(void* const* d_in, const int* in_sizes, int n_in,
                              void* d_out, int out_size) {
    const float* x         = (const float*)d_in[0];
    const void*  ei        = d_in[1];
    const int*   batch     = (const int*)d_in[2];
    const float* adapter_w = (const float*)d_in[3];
    const float* adapter_b = (const float*)d_in[4];
    const float* p1_w1 = (const float*)d_in[5];
    const float* p1_b1 = (const float*)d_in[6];
    const float* p1_lnw = (const float*)d_in[7];
    const float* p1_lnb = (const float*)d_in[8];
    const float* p1_w2 = (const float*)d_in[9];
    const float* p1_b2 = (const float*)d_in[10];
    const float* p2_w1 = (const float*)d_in[11];
    const float* p2_b1 = (const float*)d_in[12];
    const float* p2_lnw = (const float*)d_in[13];
    const float* p2_lnb = (const float*)d_in[14];
    const float* p2_w2 = (const float*)d_in[15];
    const float* p2_b2 = (const float*)d_in[16];
    const float* td1_w = (const float*)d_in[17];
    const float* td1_b = (const float*)d_in[18];
    const float* td2_w = (const float*)d_in[19];
    const float* td2_b = (const float*)d_in[20];
    const float* bu1_w = (const float*)d_in[21];
    const float* bu1_b = (const float*)d_in[22];
    const float* bu2_w = (const float*)d_in[23];
    const float* bu2_b = (const float*)d_in[24];
    const float* proj_w1 = (const float*)d_in[25];
    const float* proj_b1 = (const float*)d_in[26];
    const float* proj_w2 = (const float*)d_in[27];
    const float* proj_b2 = (const float*)d_in[28];
    float* out = (float*)d_out;
    (void)in_sizes; (void)n_in; (void)out_size;

    float *p_root, *p_s;
    __half *p_x16, *p_hxh, *p_cat1, *p_wa, *p_wc, *p_zpm, *p_zpa;
    cudaGetSymbolAddress((void**)&p_x16,  g_x16);
    cudaGetSymbolAddress((void**)&p_hxh,  g_hxh);
    cudaGetSymbolAddress((void**)&p_root, g_root);
    cudaGetSymbolAddress((void**)&p_cat1, g_cat1);
    cudaGetSymbolAddress((void**)&p_s,    g_s);
    cudaGetSymbolAddress((void**)&p_wa,   g_waT);
    cudaGetSymbolAddress((void**)&p_wc,   g_wcT);
    cudaGetSymbolAddress((void**)&p_zpm,  g_zpm);
    cudaGetSymbolAddress((void**)&p_zpa,  g_zpa);

    constexpr int SMEM3  = 6 * 128 * 40 * 2;    // 61440
    constexpr int SMEML2 = NS * 128 * 4;        // 51200
    cudaFuncSetAttribute(mmagemm<0>, cudaFuncAttributeMaxDynamicSharedMemorySize, SMEM3);
    cudaFuncSetAttribute(mmagemm<1>, cudaFuncAttributeMaxDynamicSharedMemorySize, SMEM3);
    cudaFuncSetAttribute(mmagemm<2>, cudaFuncAttributeMaxDynamicSharedMemorySize, SMEM3);
    cudaFuncSetAttribute(k_layer2,   cudaFuncAttributeMaxDynamicSharedMemorySize, SMEML2);

    const int MB = NNP / 128; // 782

    k_wprep<<<(FIN * FIN + 255) / 256, 256>>>(adapter_w, p_wa, FIN, FIN);              // 0
    k_detect<<<1, 32>>>(batch);                                                        // 1
    k_zero<<<(NN + 255) / 256, 256>>>();                                               // 2
    k_xprep<<<(NN * FIN / 8 + 255) / 256, 256>>>(x, p_x16);                            // 3
    k_count<<<(NE + 255) / 256, 256>>>(ei);                                            // 4
    k_alpha<<<(NG + 127) / 128, 128>>>();                                              // 5
    k_wprep<<<(FIN * HIDD + 255) / 256, 256>>>(td1_w, p_wc, FIN, HIDD);
    k_wprep<<<(FIN * HIDD + 255) / 256, 256>>>(bu1_w, p_wc + 128 * FIN, FIN, HIDD);

    // root-gather adapter: g_root = leakyrelu(x_root @ Wa + b)
    mmagemm<0><<<dim3(4, 8), 256, SMEM3>>>(
        p_x16, p_wa, adapter_b, nullptr, nullptr, nullptr, p_root, FIN, FIN);

    // prompts on roots + z factors
    k_promptA<<<dim3(NG / 4, 2), 128>>>(p1_w1, p1_b1, p2_w1, p2_b1);
    k_promptLN<<<dim3(NG, 2), 128>>>(p1_lnw, p1_lnb, p2_lnw, p2_lnb);
    k_promptB<<<dim3(NG / 4, 2), 512>>>(p1_w2, p1_b2, p2_w2, p2_b2);
    k_zprep<<<(NG * FIN + 255) / 256, 256>>>(p_zpm, p_zpa);

    // main adapter with fused z epilogue -> A_z (fp16)
    mmagemm<1><<<dim3(4, MB), 256, SMEM3>>>(
        p_x16, p_wa, adapter_b, p_zpm, p_zpa, p_hxh, nullptr, FIN, FIN);

    // GCN layer 1 linear (td|bu concat, N=256), fp16 cat1 output
    mmagemm<2><<<dim3(2, MB), 256, SMEM3>>>(
        p_hxh, p_wc, nullptr, nullptr, nullptr, p_cat1, nullptr, 256, FIN);

    // fused layer-1 aggregation + layer-2 collapse
    k_layer2<<<NG, 256, SMEML2>>>(td1_b, bu1_b, p_s);
    k_small<<<NG, 128>>>(td2_w, td2_b, bu2_w, bu2_b);

    // projection head
    k_projA<<<NG, 256>>>(proj_w1, proj_b1);
    k_projB<<<NG, 128>>>(proj_w2, proj_b2, out);
}

// round 17
// speedup vs baseline: 1.1644x; 1.0170x over previous
#include <cuda_runtime.h>
#include <cuda_fp16.h>
#include <math.h>
#include <stdint.h>

#define NN   100000
#define NNP  100096      // 782 * 128
#define NG   1000
#define NS   100
#define NE   99000
#define FIN  512
#define HIDD 128
#define FO   64

// ---------------- scratch (device globals; no allocations allowed) ----------------
__device__ __align__(16) __half g_x16[NNP * FIN];               // x in fp16 (rows >= NN stay 0)
__device__ __align__(16) __half g_hxh[NNP * FIN];               // A_z fp16
__device__ __align__(16) float g_root[NG * FIN];                // fp32 root hx rows
__device__ __align__(16) __half g_cat1[NNP * 256];              // [td1 | bu1] GEMM output (fp16)
__device__ __align__(16) __half g_waT[FIN * FIN];
__device__ __align__(16) __half g_wcT[256 * FIN];
__device__ __align__(16) __half g_zpm[NG * FIN];
__device__ __align__(16) __half g_zpa[NG * FIN];
__device__ __align__(16) float g_tp[2 * NG * HIDD];
__device__ __align__(16) float g_tln[2 * NG * HIDD];
__device__ __align__(16) float g_pm[2 * NG * FIN];
__device__ __align__(16) float g_s[NG * 256];                   // [s_td | s_bu] per graph
__device__ __align__(16) float g_alpha[NG];
__device__ __align__(16) float g_stats[4];
__device__ __align__(16) int   g_cnt[NN];
__device__ __align__(16) int   g_parent[NN];
__device__ int   g_idx64;

// ---------------- helpers ----------------
static __device__ __forceinline__ uint32_t smem_u32(const void* p) {
    uint32_t a;
    asm("{ .reg .u64 t; cvta.to.shared.u64 t, %1; cvt.u32.u64 %0, t; }" : "=r"(a) : "l"(p));
    return a;
}
#define CP_ASYNC16(dst_u32, src) \
    asm volatile("cp.async.cg.shared.global [%0], [%1], 16;" :: "r"(dst_u32), "l"(src))
#define CP_COMMIT() asm volatile("cp.async.commit_group;" ::: "memory")
#define CP_WAIT1()  asm volatile("cp.async.wait_group 1;" ::: "memory")

#define MMA_F16(d, a, b0, b1) \
    asm volatile("mma.sync.aligned.m16n8k16.row.col.f32.f16.f16.f32 " \
        "{%0,%1,%2,%3}, {%4,%5,%6,%7}, {%8,%9}, {%0,%1,%2,%3};" \
        : "+f"((d)[0]), "+f"((d)[1]), "+f"((d)[2]), "+f"((d)[3]) \
        : "r"((a)[0]), "r"((a)[1]), "r"((a)[2]), "r"((a)[3]), "r"(b0), "r"(b1))

#define LDSM_X4(r, addr) \
    asm volatile("ldmatrix.sync.aligned.m8n8.x4.shared.b16 {%0,%1,%2,%3}, [%4];" \
        : "=r"((r)[0]), "=r"((r)[1]), "=r"((r)[2]), "=r"((r)[3]) : "r"(addr))

// ---------------- index dtype probe + edge accessors ----------------
__device__ __forceinline__ int esrc(const void* ei, int e) {
    return g_idx64 ? (int)((const long long*)ei)[e] : ((const int*)ei)[e];
}
__device__ __forceinline__ int edst(const void* ei, int e) {
    return g_idx64 ? (int)((const long long*)ei)[NE + e] : ((const int*)ei)[NE + e];
}

// ---------------- small graph kernels ----------------
__global__ void k_init(const int* batch) {
    int i = blockIdx.x * blockDim.x + threadIdx.x;
    if (i == 0) g_idx64 = (batch[150] == 1) ? 0 : 1;
    if (i < NN) g_cnt[i] = 0;
    if (i < 4) g_stats[i] = 0.f;
}
__global__ void k_count(const void* ei) {
    int e = blockIdx.x * blockDim.x + threadIdx.x;
    if (e >= NE) return;
    int s = esrc(ei, e), d = edst(ei, e);
    atomicAdd(&g_cnt[s], 1);
    g_parent[d] = s;
}
__global__ void k_alpha() {
    int g = blockIdx.x * blockDim.x + threadIdx.x;
    if (g >= NG) return;
    float cnt = (float)g_cnt[g * NS];
    float t = (cnt / (float)NS - 0.3f) / 0.1f;
    g_alpha[g] = 1.f / (1.f + expf(-t));
}

// ---------------- preps ----------------
__global__ void k_wprep(const float* __restrict__ w, __half* __restrict__ hi, int K, int Nw) {
    int i = blockIdx.x * blockDim.x + threadIdx.x;
    if (i >= K * Nw) return;
    int k = i / Nw, n = i % Nw;
    hi[(size_t)n * K + k] = __float2half(w[i]);
}
__global__ void k_xprep(const float* __restrict__ x, __half* __restrict__ x16) {
    int i = blockIdx.x * blockDim.x + threadIdx.x;   // over NN*FIN/8
    if (i >= NN * FIN / 8) return;
    float4 a = ((const float4*)x)[i * 2];
    float4 b = ((const float4*)x)[i * 2 + 1];
    union { __half h[8]; uint4 u; } H;
    H.h[0] = __float2half(a.x); H.h[1] = __float2half(a.y);
    H.h[2] = __float2half(a.z); H.h[3] = __float2half(a.w);
    H.h[4] = __float2half(b.x); H.h[5] = __float2half(b.y);
    H.h[6] = __float2half(b.z); H.h[7] = __float2half(b.w);
    ((uint4*)x16)[i] = H.u;
}
__global__ void k_zprep(__half* __restrict__ zpm, __half* __restrict__ zpa) {
    int i = blockIdx.x * blockDim.x + threadIdx.x;
    if (i >= NG * FIN) return;
    int g = i / FIN;
    float a = g_alpha[g];
    zpm[i] = __float2half((1.f - a) * g_pm[i] + a);
    zpa[i] = __float2half(a * g_pm[NG * FIN + i]);
}

// ---------------- HMMA GEMM, fp16, 8 warps (4x2), 3-stage, 1 barrier/iter ----
// MODE 0 (root):    A rows gathered (r -> r*NS); epilogue -> fp32 rootOut (r<NG).
// MODE 1 (adapter): A = x16; epilogue bias+leakyrelu+z -> fp16 Ch.
// MODE 2 (gemm1):   A = A_z; fp16 Ch epilogue (cat1).
template <int MODE>
__global__ void __launch_bounds__(256, 2) mmagemm(
    const __half* __restrict__ Asrc, const __half* __restrict__ Bh,
    const float* __restrict__ bias,
    const __half* __restrict__ zpm, const __half* __restrict__ zpa,
    __half* __restrict__ Ch, float* __restrict__ rootOut,
    int Ntot, int K)
{
    constexpr int ASZ = 128 * 40;       // elems per stage buffer (10240 B)
    extern __shared__ __align__(16) __half sm[];
    __half* sA = sm;                           // [0, 30720): 3 stages
    __half* sB = sm + 3 * ASZ;                 // [30720, 61440): 3 stages

    const int tid = threadIdx.x, lane = tid & 31, w = tid >> 5;
    const int m0 = blockIdx.y * 128, n0 = blockIdx.x * 128;
    const int warpM = (w & 3) * 32;
    const int warpN = (w >> 2) * 64;
    const int r4 = lane >> 2, q = lane & 3;

    float acc[2][8][4];
#pragma unroll
    for (int mt = 0; mt < 2; mt++)
#pragma unroll
        for (int nt = 0; nt < 8; nt++)
#pragma unroll
            for (int i = 0; i < 4; i++) acc[mt][nt][i] = 0.f;

    const int KS = K >> 5;

    auto stage = [&](int ks, int s) {
#pragma unroll
        for (int c = tid; c < 512; c += 256) {     // A tile: 128 rows x 4 chunks
            int r = c >> 2, qq = c & 3;
            int srow = (MODE == 0) ? min(m0 + r, NG - 1) * NS : (m0 + r);
            const __half* src = Asrc + (size_t)srow * K + ks * 32 + qq * 8;
            CP_ASYNC16(smem_u32(sA + s * ASZ + r * 40) + qq * 16, src);
        }
#pragma unroll
        for (int c = tid; c < 512; c += 256) {     // B tile
            int r = c >> 2, qq = c & 3;
            const __half* src = Bh + (size_t)(n0 + r) * K + ks * 32 + qq * 8;
            CP_ASYNC16(smem_u32(sB + s * ASZ + r * 40) + qq * 16, src);
        }
    };

    // ldmatrix per-lane base addresses
    const int mat = lane >> 3, mrow = lane & 7;
    const uint32_t smb = smem_u32(sm);
    const uint32_t aBase = smb + (uint32_t)((warpM + (mat & 1) * 8 + mrow) * 80 + (mat >> 1) * 16);
    const uint32_t bBase = smb + 30720u + (uint32_t)((warpN + (mat & 1) * 8 + mrow) * 80 + (mat >> 1) * 16);

    // ---- prologue ----
    stage(0, 0); CP_COMMIT();
    stage(1, 1); CP_COMMIT();
    CP_WAIT1();
    __syncthreads();

    for (int ks = 0; ks < KS; ks++) {
        const int s = ks % 3;
        const bool pre = (ks + 2 < KS);
        if (pre) {
            stage(ks + 2, (ks + 2) % 3);
            CP_COMMIT();
        } else {
            CP_COMMIT();
        }

        const uint32_t aS = aBase + (uint32_t)s * 10240u;
        const uint32_t bS = bBase + (uint32_t)s * 10240u;
#pragma unroll
        for (int k16 = 0; k16 < 2; k16++) {
            uint32_t ah[2][4];
            LDSM_X4(ah[0], aS + k16 * 32u);
            LDSM_X4(ah[1], aS + 1280u + k16 * 32u);
            uint32_t bp[2][4];
            LDSM_X4(bp[0], bS + k16 * 32u);
#pragma unroll
            for (int nn = 0; nn < 4; nn++) {       // B fragment ping-pong
                const int cur = nn & 1;
                if (nn < 3) LDSM_X4(bp[cur ^ 1], bS + (nn + 1) * 1280u + k16 * 32u);
#pragma unroll
                for (int e = 0; e < 2; e++) {
                    const int nt = 2 * nn + e;
                    MMA_F16(acc[0][nt], ah[0], bp[cur][e], bp[cur][e + 2]);
                    MMA_F16(acc[1][nt], ah[1], bp[cur][e], bp[cur][e + 2]);
                }
            }
        }
        CP_WAIT1();
        __syncthreads();
    }

    // ---- epilogue ----
#pragma unroll
    for (int mt = 0; mt < 2; mt++) {
#pragma unroll
        for (int nt = 0; nt < 8; nt++) {
            int row = m0 + warpM + mt * 16 + r4;
            int col = n0 + warpN + nt * 8 + q * 2;
            float v0 = acc[mt][nt][0], v1 = acc[mt][nt][1];
            float v2 = acc[mt][nt][2], v3 = acc[mt][nt][3];
            if (MODE == 0) {
                float b0 = bias[col], b1 = bias[col + 1];
                v0 += b0; v1 += b1; v2 += b0; v3 += b1;
                v0 = v0 > 0.f ? v0 : 0.01f * v0;
                v1 = v1 > 0.f ? v1 : 0.01f * v1;
                v2 = v2 > 0.f ? v2 : 0.01f * v2;
                v3 = v3 > 0.f ? v3 : 0.01f * v3;
                if (row < NG)
                    *(float2*)(rootOut + (size_t)row * FIN + col) = make_float2(v0, v1);
                if (row + 8 < NG)
                    *(float2*)(rootOut + (size_t)(row + 8) * FIN + col) = make_float2(v2, v3);
            } else if (MODE == 1) {
                float b0 = bias[col], b1 = bias[col + 1];
                v0 += b0; v1 += b1; v2 += b0; v3 += b1;
                v0 = v0 > 0.f ? v0 : 0.01f * v0;
                v1 = v1 > 0.f ? v1 : 0.01f * v1;
                v2 = v2 > 0.f ? v2 : 0.01f * v2;
                v3 = v3 > 0.f ? v3 : 0.01f * v3;
                int ga = row / NS, gb2 = (row + 8) / NS;
                float2 fm0 = __half22float2(*(const __half2*)(zpm + (size_t)ga * FIN + col));
                float2 fa0 = __half22float2(*(const __half2*)(zpa + (size_t)ga * FIN + col));
                float2 fm1 = __half22float2(*(const __half2*)(zpm + (size_t)gb2 * FIN + col));
                float2 fa1 = __half22float2(*(const __half2*)(zpa + (size_t)gb2 * FIN + col));
                v0 = v0 * fm0.x + fa0.x; v1 = v1 * fm0.y + fa0.y;
                v2 = v2 * fm1.x + fa1.x; v3 = v3 * fm1.y + fa1.y;
                *(__half2*)(Ch + (size_t)row * Ntot + col) = __floats2half2_rn(v0, v1);
                *(__half2*)(Ch + (size_t)(row + 8) * Ntot + col) = __floats2half2_rn(v2, v3);
            } else {
                *(__half2*)(Ch + (size_t)row * Ntot + col) = __floats2half2_rn(v0, v1);
                *(__half2*)(Ch + (size_t)(row + 8) * Ntot + col) = __floats2half2_rn(v2, v3);
            }
        }
    }
}

// ---------------- prompt kernels (4 graphs per block) ----------------
__global__ void k_promptA(const float* __restrict__ w1a, const float* __restrict__ b1a,
                          const float* __restrict__ w1b, const float* __restrict__ b1b) {
    const int gb = blockIdx.x * 4, which = blockIdx.y, j = threadIdx.x;  // 128 threads
    const float* w = which ? w1b : w1a;
    const float* b = which ? b1b : b1a;
    __shared__ float rfs[4 * 128];
    float acc[4];
    float bj = b[j];
#pragma unroll
    for (int g = 0; g < 4; g++) acc[g] = bj;
    for (int kc = 0; kc < 4; kc++) {
        __syncthreads();
#pragma unroll
        for (int idx = j; idx < 512; idx += 128) {
            int g = idx >> 7, k = idx & 127;
            rfs[idx] = g_root[(size_t)(gb + g) * FIN + kc * 128 + k];
        }
        __syncthreads();
#pragma unroll 4
        for (int k = 0; k < 128; k++) {
            float wv = w[(kc * 128 + k) * HIDD + j];
            acc[0] = fmaf(rfs[k], wv, acc[0]);
            acc[1] = fmaf(rfs[128 + k], wv, acc[1]);
            acc[2] = fmaf(rfs[256 + k], wv, acc[2]);
            acc[3] = fmaf(rfs[384 + k], wv, acc[3]);
        }
    }
    float l1 = 0.f, l2 = 0.f;
#pragma unroll
    for (int g = 0; g < 4; g++) {
        g_tp[which * NG * HIDD + (gb + g) * HIDD + j] = acc[g];
        l1 += acc[g];
        l2 += acc[g] * acc[g];
    }
    __shared__ float s1[128], s2[128];
    s1[j] = l1; s2[j] = l2;
    __syncthreads();
    for (int o = 64; o > 0; o >>= 1) {
        if (j < o) { s1[j] += s1[j + o]; s2[j] += s2[j + o]; }
        __syncthreads();
    }
    if (j == 0) {
        atomicAdd(&g_stats[which * 2 + 0], s1[0]);
        atomicAdd(&g_stats[which * 2 + 1], s2[0]);
    }
}
__global__ void k_promptLN(const float* __restrict__ lnwa, const float* __restrict__ lnba,
                           const float* __restrict__ lnwb, const float* __restrict__ lnbb) {
    int g = blockIdx.x, which = blockIdx.y, j = threadIdx.x;
    const float* lw = which ? lnwb : lnwa;
    const float* lb = which ? lnbb : lnba;
    const float inv_n = 1.f / (float)(NG * HIDD);
    float m = g_stats[which * 2 + 0] * inv_n;
    float msq = fmaxf(g_stats[which * 2 + 1] * inv_n - m * m, 0.f);
    float denom = sqrtf(msq) + 1e-5f;
    float t = g_tp[which * NG * HIDD + g * HIDD + j];
    float v = (t - m) / denom * lw[j] + lb[j];
    g_tln[which * NG * HIDD + g * HIDD + j] = tanhf(v);
}
__global__ void k_promptB(const float* __restrict__ w2a, const float* __restrict__ b2a,
                          const float* __restrict__ w2b, const float* __restrict__ b2b) {
    const int gb = blockIdx.x * 4, which = blockIdx.y, j = threadIdx.x;  // 512 threads
    const float* w = which ? w2b : w2a;
    const float* b = which ? b2b : b2a;
    __shared__ float ts[4 * 128];
    if (j < 512) {
        int g = j >> 7, k = j & 127;
        ts[j] = g_tln[which * NG * HIDD + (gb + g) * HIDD + k];
    }
    __syncthreads();
    float acc[4];
    float bj = b[j];
#pragma unroll
    for (int g = 0; g < 4; g++) acc[g] = bj;
#pragma unroll 4
    for (int k = 0; k < 128; k++) {
        float wv = w[k * FIN + j];
        acc[0] = fmaf(ts[k], wv, acc[0]);
        acc[1] = fmaf(ts[128 + k], wv, acc[1]);
        acc[2] = fmaf(ts[256 + k], wv, acc[2]);
        acc[3] = fmaf(ts[384 + k], wv, acc[3]);
    }
#pragma unroll
    for (int g = 0; g < 4; g++)
        g_pm[which * NG * FIN + (gb + g) * FIN + j] = acc[g];
}

// ---------------- fused layer-1 aggregation + layer-2 collapse (TD/BU concurrent) ----------------
__global__ void k_layer2(const float* __restrict__ td1_b, const float* __restrict__ bu1_b,
                         float* __restrict__ s_out) {
    extern __shared__ float buacc[];            // [NS][128], BU half only
    __shared__ float dinvb[NS], cntS[NS];
    __shared__ int   pl[NS];
    const int g = blockIdx.x, t = threadIdx.x;  // 256 threads
    for (int n = t; n < NS; n += 256) {
        int i = g * NS + n;
        int c = g_cnt[i];
        cntS[n]  = (float)c;
        dinvb[n] = rsqrtf((float)(c + 1));
        pl[n]    = n ? (g_parent[i] - g * NS) : 0;
    }
    __syncthreads();
    if (t < 128) {
        const int f = t;
        const float btd = td1_b[f];
        float s_td = 0.f;
        for (int n = 0; n < NS; n++) {
            float utd = __half2float(g_cat1[(size_t)(g * NS + n) * 256 + f]);
            float v, c_td;
            if (n) {
                int p = pl[n];
                float dp = p ? 0.70710678118654752f : 1.0f;
                float up = __half2float(g_cat1[(size_t)(g * NS + p) * 256 + f]);
                v = utd * 0.5f + up * dp * 0.70710678118654752f + btd;
                c_td = 0.5f + 0.5f * cntS[n];
            } else {
                v = utd + btd;
                c_td = 1.0f + 0.70710678118654752f * cntS[0];
            }
            v = v > 0.f ? v : 0.f;
            s_td += c_td * v;
        }
        s_out[g * 256 + f] = s_td;
    } else {
        const int f = t - 128;
        const float bbu = bu1_b[f];
        for (int n = 0; n < NS; n++) {
            float ubu = __half2float(g_cat1[(size_t)(g * NS + n) * 256 + 128 + f]);
            float db = dinvb[n];
            if (n) {
                buacc[pl[n] * 128 + f] += ubu * db * dinvb[pl[n]];
                buacc[n * 128 + f] = ubu * db * db;
            } else {
                buacc[f] = ubu * db * db;
            }
        }
        float s_bu = 0.f;
        for (int n = 0; n < NS; n++) {
            float v = buacc[n * 128 + f] + bbu;
            v = v > 0.f ? v : 0.f;
            float db = dinvb[n];
            float c_bu = db * db + (n ? db * dinvb[pl[n]] : 0.f);
            s_bu += c_bu * v;
        }
        s_out[g * 256 + 128 + f] = s_bu;
    }
}

// ---------------- fused projection tail: small GEMM + projA + projB ----------------
__global__ void k_projfused(const float* __restrict__ w2td, const float* __restrict__ td2_b,
                            const float* __restrict__ w2bu, const float* __restrict__ bu2_b,
                            const float* __restrict__ pw1, const float* __restrict__ pb1,
                            const float* __restrict__ pw2, const float* __restrict__ pb2,
                            float* __restrict__ out) {
    const int g = blockIdx.x, t = threadIdx.x;  // 256 threads
    __shared__ float sS[256];
    __shared__ float hc[128];
    __shared__ float r1s[256];
    sS[t] = g_s[g * 256 + t];
    __syncthreads();
    // phase 1: small layer-2 GEMM -> hc
    if (t < 128) {
        float acc;
        if (t < FO) {
            acc = (float)NS * bu2_b[t];
#pragma unroll 4
            for (int k = 0; k < HIDD; k++) acc = fmaf(sS[128 + k], w2bu[k * FO + t], acc);
        } else {
            int jj = t - FO;
            acc = (float)NS * td2_b[jj];
#pragma unroll 4
            for (int k = 0; k < HIDD; k++) acc = fmaf(sS[k], w2td[k * FO + jj], acc);
        }
        hc[t] = acc;
    }
    __syncthreads();
    // phase 2: projA -> r1s
    {
        float acc = pb1[t];
#pragma unroll 4
        for (int k = 0; k < 128; k++) acc = fmaf(hc[k], pw1[k * 256 + t], acc);
        r1s[t] = acc > 0.f ? acc : 0.f;
    }
    __syncthreads();
    // phase 3: projB -> out
    if (t < 128) {
        float acc = pb2[t];
#pragma unroll 4
        for (int k = 0; k < 256; k++) acc = fmaf(r1s[k], pw2[k * 128 + t], acc);
        out[g * 128 + t] = acc;
    }
}

// ---------------- launch ----------------
extern "C" void kernel_launch(void* const* d_in, const int* in_sizes, int n_in,
                              void* d_out, int out_size) {
    const float* x         = (const float*)d_in[0];
    const void*  ei        = d_in[1];
    const int*   batch     = (const int*)d_in[2];
    const float* adapter_w = (const float*)d_in[3];
    const float* adapter_b = (const float*)d_in[4];
    const float* p1_w1 = (const float*)d_in[5];
    const float* p1_b1 = (const float*)d_in[6];
    const float* p1_lnw = (const float*)d_in[7];
    const float* p1_lnb = (const float*)d_in[8];
    const float* p1_w2 = (const float*)d_in[9];
    const float* p1_b2 = (const float*)d_in[10];
    const float* p2_w1 = (const float*)d_in[11];
    const float* p2_b1 = (const float*)d_in[12];
    const float* p2_lnw = (const float*)d_in[13];
    const float* p2_lnb = (const float*)d_in[14];
    const float* p2_w2 = (const float*)d_in[15];
    const float* p2_b2 = (const float*)d_in[16];
    const float* td1_w = (const float*)d_in[17];
    const float* td1_b = (const float*)d_in[18];
    const float* td2_w = (const float*)d_in[19];
    const float* td2_b = (const float*)d_in[20];
    const float* bu1_w = (const float*)d_in[21];
    const float* bu1_b = (const float*)d_in[22];
    const float* bu2_w = (const float*)d_in[23];
    const float* bu2_b = (const float*)d_in[24];
    const float* proj_w1 = (const float*)d_in[25];
    const float* proj_b1 = (const float*)d_in[26];
    const float* proj_w2 = (const float*)d_in[27];
    const float* proj_b2 = (const float*)d_in[28];
    float* out = (float*)d_out;
    (void)in_sizes; (void)n_in; (void)out_size;

    float *p_root, *p_s;
    __half *p_x16, *p_hxh, *p_cat1, *p_wa, *p_wc, *p_zpm, *p_zpa;
    cudaGetSymbolAddress((void**)&p_x16,  g_x16);
    cudaGetSymbolAddress((void**)&p_hxh,  g_hxh);
    cudaGetSymbolAddress((void**)&p_root, g_root);
    cudaGetSymbolAddress((void**)&p_cat1, g_cat1);
    cudaGetSymbolAddress((void**)&p_s,    g_s);
    cudaGetSymbolAddress((void**)&p_wa,   g_waT);
    cudaGetSymbolAddress((void**)&p_wc,   g_wcT);
    cudaGetSymbolAddress((void**)&p_zpm,  g_zpm);
    cudaGetSymbolAddress((void**)&p_zpa,  g_zpa);

    constexpr int SMEM3  = 6 * 128 * 40 * 2;    // 61440
    constexpr int SMEML2 = NS * 128 * 4;        // 51200
    cudaFuncSetAttribute(mmagemm<0>, cudaFuncAttributeMaxDynamicSharedMemorySize, SMEM3);
    cudaFuncSetAttribute(mmagemm<1>, cudaFuncAttributeMaxDynamicSharedMemorySize, SMEM3);
    cudaFuncSetAttribute(mmagemm<2>, cudaFuncAttributeMaxDynamicSharedMemorySize, SMEM3);
    cudaFuncSetAttribute(k_layer2,   cudaFuncAttributeMaxDynamicSharedMemorySize, SMEML2);

    const int MB = NNP / 128; // 782

    k_wprep<<<(FIN * FIN + 255) / 256, 256>>>(adapter_w, p_wa, FIN, FIN);              // 0
    k_init<<<(NN + 255) / 256, 256>>>(batch);                                          // 1
    k_count<<<(NE + 255) / 256, 256>>>(ei);                                            // 2
    k_xprep<<<(NN * FIN / 8 + 255) / 256, 256>>>(x, p_x16);                            // 3
    k_alpha<<<(NG + 127) / 128, 128>>>();                                              // 4
    k_wprep<<<(FIN * HIDD + 255) / 256, 256>>>(td1_w, p_wc, FIN, HIDD);
    k_wprep<<<(FIN * HIDD + 255) / 256, 256>>>(bu1_w, p_wc + 128 * FIN, FIN, HIDD);

    // root-gather adapter: g_root = leakyrelu(x_root @ Wa + b)
    mmagemm<0><<<dim3(4, 8), 256, SMEM3>>>(
        p_x16, p_wa, adapter_b, nullptr, nullptr, nullptr, p_root, FIN, FIN);

    // prompts on roots + z factors
    k_promptA<<<dim3(NG / 4, 2), 128>>>(p1_w1, p1_b1, p2_w1, p2_b1);
    k_promptLN<<<dim3(NG, 2), 128>>>(p1_lnw, p1_lnb, p2_lnw, p2_lnb);
    k_promptB<<<dim3(NG / 4, 2), 512>>>(p1_w2, p1_b2, p2_w2, p2_b2);
    k_zprep<<<(NG * FIN + 255) / 256, 256>>>(p_zpm, p_zpa);

    // main adapter with fused z epilogue -> A_z (fp16)
    mmagemm<1><<<dim3(4, MB), 256, SMEM3>>>(
        p_x16, p_wa, adapter_b, p_zpm, p_zpa, p_hxh, nullptr, FIN, FIN);

    // GCN layer 1 linear (td|bu concat, N=256), fp16 cat1 output
    mmagemm<2><<<dim3(2, MB), 256, SMEM3>>>(
        p_hxh, p_wc, nullptr, nullptr, nullptr, p_cat1, nullptr, 256, FIN);

    // fused layer-1 aggregation + layer-2 collapse
    k_layer2<<<NG, 256, SMEML2>>>(td1_b, bu1_b, p_s);

    // fused projection tail (small GEMM + projA + projB)
    k_projfused<<<NG, 256>>>(td2_w, td2_b, bu2_w, bu2_b,
                             proj_w1, proj_b1, proj_w2, proj_b2, out);
}